// round 12
// baseline (speedup 1.0000x reference)
#include <cuda_runtime.h>
#include <cuda_bf16.h>
#include <math.h>
#include <stdint.h>

typedef __nv_bfloat16 bf16;

#define Dq 1024
#define Pq 128
#define Bq 4096
#define Nq 8192
#define Cq 1000
#define Mall 20480              // 4096 + 2*8192

// ---------------- scratch (static device memory; no allocations) -----------
__device__ bf16  g_xb  [(size_t)Mall * Dq];
__device__ bf16  g_W1b [Pq * Dq];
__device__ bf16  g_W2b [Pq * Pq];
__device__ bf16  g_W3b [3 * Dq * Pq];
__device__ bf16  g_Wpb [Dq * Dq];
__device__ bf16  g_H1b [(size_t)Mall * Pq];
__device__ bf16  g_H2b [(size_t)Mall * Pq];
__device__ bf16  g_Qb  [Bq * Dq];
__device__ bf16  g_Kall[(size_t)2 * Nq * Dq];
__device__ bf16  g_Vall[(size_t)2 * Nq * Dq];
__device__ bf16  g_Sall[(size_t)Bq * 2 * Nq];
__device__ bf16  g_AVal[(size_t)2 * Bq * Dq];
__device__ float g_F   [(size_t)2 * Bq * Dq];
__device__ float g_G   [Bq * Dq];
__device__ bf16  g_Ap  [(size_t)Bq * 3 * Dq];
__device__ bf16  g_Bp  [(size_t)Cq * 3 * Dq];
__device__ int8_t  g_Q8[Bq * Dq];
__device__ int8_t  g_K8[(size_t)2 * Nq * Dq];
__device__ unsigned g_amax[2];

// ---------------- helpers ---------------------------------------------------
__device__ __forceinline__ uint32_t s2u(const void* p) {
    uint32_t a;
    asm("{ .reg .u64 t; cvta.to.shared.u64 t, %1; cvt.u32.u64 %0, t; }"
        : "=r"(a) : "l"(p));
    return a;
}
__device__ __forceinline__ void ldmx4(uint32_t* r, uint32_t a) {
    asm volatile("ldmatrix.sync.aligned.m8n8.x4.shared.b16 {%0,%1,%2,%3}, [%4];"
                 : "=r"(r[0]), "=r"(r[1]), "=r"(r[2]), "=r"(r[3]) : "r"(a));
}
__device__ __forceinline__ void ldmx4t(uint32_t* r, uint32_t a) {
    asm volatile("ldmatrix.sync.aligned.m8n8.x4.trans.shared.b16 {%0,%1,%2,%3}, [%4];"
                 : "=r"(r[0]), "=r"(r[1]), "=r"(r[2]), "=r"(r[3]) : "r"(a));
}
__device__ __forceinline__ void mma16816(float* c, const uint32_t* a, const uint32_t* b) {
    asm volatile("mma.sync.aligned.m16n8k16.row.col.f32.bf16.bf16.f32 "
                 "{%0,%1,%2,%3}, {%4,%5,%6,%7}, {%8,%9}, {%0,%1,%2,%3};"
                 : "+f"(c[0]), "+f"(c[1]), "+f"(c[2]), "+f"(c[3])
                 : "r"(a[0]), "r"(a[1]), "r"(a[2]), "r"(a[3]),
                   "r"(b[0]), "r"(b[1]));
}
__device__ __forceinline__ void mma16832s(int* c, const uint32_t* a, const uint32_t* b) {
    asm volatile("mma.sync.aligned.m16n8k32.row.col.s32.s8.s8.s32 "
                 "{%0,%1,%2,%3}, {%4,%5,%6,%7}, {%8,%9}, {%0,%1,%2,%3};"
                 : "+r"(c[0]), "+r"(c[1]), "+r"(c[2]), "+r"(c[3])
                 : "r"(a[0]), "r"(a[1]), "r"(a[2]), "r"(a[3]),
                   "r"(b[0]), "r"(b[1]));
}
__device__ __forceinline__ void cp16(uint32_t dst, const void* src) {
    asm volatile("cp.async.cg.shared.global [%0], [%1], 16;"
                 :: "r"(dst), "l"(src));
}
__device__ __forceinline__ void cp16z(uint32_t dst, const void* src, int sz) {
    asm volatile("cp.async.cg.shared.global [%0], [%1], 16, %2;"
                 :: "r"(dst), "l"(src), "r"(sz));
}
__device__ __forceinline__ void cp_commit() {
    asm volatile("cp.async.commit_group;" ::: "memory");
}

// ---------------- mma.sync GEMM (bf16) --------------------------------------
#define SROW 80
#define ATILE_B (128 * SROW)           // 10240
#define NSTAGE  3

#define MODE_SMUL   0
#define MODE_BNRELU 1
#define MODE_QKV    2
#define MODE_RESID  3
#define MODE_LS     4

template <int BN, bool TRANSB>
__device__ __forceinline__ void stage_load(const bf16* __restrict__ A,
                                           const bf16* __restrict__ Bm,
                                           int N_, int K_, int lda,
                                           int m0, int n0, int k0,
                                           uint32_t sbase, int tid)
{
    const int T = 2 * BN;
#pragma unroll
    for (int i = tid; i < 512; i += T) {
        const int row = i >> 2, ch = i & 3;
        cp16(sbase + row * SROW + ch * 16,
             A + (size_t)(m0 + row) * lda + k0 + ch * 8);
    }
    if (TRANSB) {
#pragma unroll
        for (int i = tid; i < 4 * BN; i += T) {
            const int row = i >> 2, ch = i & 3;
            const int grow = n0 + row;
            const int v = (grow < N_);
            cp16z(sbase + ATILE_B + row * SROW + ch * 16,
                  Bm + (size_t)(v ? grow : 0) * K_ + k0 + ch * 8, v ? 16 : 0);
        }
    } else {
        constexpr int CPR = BN / 8;
        constexpr int BROW = 2 * BN + 16;
#pragma unroll
        for (int i = tid; i < 32 * CPR; i += T) {
            const int kk = i / CPR, ch = i % CPR;
            cp16(sbase + ATILE_B + kk * BROW + ch * 16,
                 Bm + (size_t)(k0 + kk) * N_ + n0 + ch * 8);
        }
    }
}

template <int BN, bool TRANSB>
__device__ __forceinline__ void compute_stage(uint32_t sbase, int lane,
                                              int wm, int wn,
                                              float acc[4][4][4])
{
    constexpr int BROW = 2 * BN + 16;
    const uint32_t aBase = sbase + (wm * 64 + (lane & 15)) * SROW + (lane >> 4) * 16;
    uint32_t bBase;
    if (TRANSB) {
        bBase = sbase + ATILE_B +
                (wn * 32 + ((lane >> 4) << 3) + (lane & 7)) * SROW +
                (((lane >> 3) & 1) << 4);
    } else {
        bBase = sbase + ATILE_B +
                ((lane & 7) + (((lane >> 3) & 1) << 3)) * BROW +
                (wn * 32 + (lane >> 4) * 8) * 2;
    }
#pragma unroll
    for (int kh = 0; kh < 2; ++kh) {
        uint32_t af[4][4];
#pragma unroll
        for (int tm = 0; tm < 4; ++tm)
            ldmx4(af[tm], aBase + tm * 16 * SROW + kh * 32);
        uint32_t bfr[4][2];
#pragma unroll
        for (int tp = 0; tp < 2; ++tp) {
            uint32_t r[4];
            if (TRANSB) ldmx4(r, bBase + tp * 16 * SROW + kh * 32);
            else        ldmx4t(r, bBase + kh * 16 * BROW + tp * 32);
            bfr[2 * tp][0] = r[0];  bfr[2 * tp][1] = r[1];
            bfr[2 * tp + 1][0] = r[2]; bfr[2 * tp + 1][1] = r[3];
        }
#pragma unroll
        for (int tm = 0; tm < 4; ++tm)
#pragma unroll
            for (int tn = 0; tn < 4; ++tn)
                mma16816(acc[tm][tn], af[tm], bfr[tn]);
    }
}

template <int BN, bool TRANSB>
__global__ __launch_bounds__(2 * BN)
void tc_gemm(const bf16* __restrict__ A, const bf16* __restrict__ Bm,
             int M, int N, int K, int lda,
             size_t aOff, size_t bOff, size_t cOffB,
             int mode, float scale,
             const float* __restrict__ bias, const float* __restrict__ gam,
             const float* __restrict__ bet, const float* __restrict__ mean,
             const float* __restrict__ var, const float* __restrict__ resid,
             const float* __restrict__ lsp,
             void* __restrict__ Cout,
             bf16* __restrict__ qo, bf16* __restrict__ ko, bf16* __restrict__ vo,
             unsigned* __restrict__ amaxp)
{
    constexpr int NW = BN / 32;
    constexpr int BSTAGE = TRANSB ? BN * SROW : 32 * (2 * BN + 16);
    constexpr int STAGE = ATILE_B + BSTAGE;
    extern __shared__ char smem[];
    const uint32_t sb = s2u(smem);
    A  += blockIdx.z * aOff;
    Bm += blockIdx.z * bOff;
    Cout = (void*)((char*)Cout + (size_t)blockIdx.z * cOffB);
    const int tid  = threadIdx.x;
    const int lane = tid & 31;
    const int wid  = tid >> 5;
    const int wm = wid / NW, wn = wid % NW;
    const int m0 = blockIdx.y * 128;
    const int n0 = blockIdx.x * BN;
    const int NC = K >> 5;

    float acc[4][4][4];
#pragma unroll
    for (int a = 0; a < 4; ++a)
#pragma unroll
        for (int b = 0; b < 4; ++b)
#pragma unroll
            for (int c = 0; c < 4; ++c) acc[a][b][c] = 0.f;

#pragma unroll
    for (int s = 0; s < 2; ++s) {
        stage_load<BN, TRANSB>(A, Bm, N, K, lda, m0, n0, s * 32, sb + s * STAGE, tid);
        cp_commit();
    }

    for (int i = 0; i < NC; ++i) {
        asm volatile("cp.async.wait_group 1;" ::: "memory");
        __syncthreads();
        compute_stage<BN, TRANSB>(sb + (i % NSTAGE) * STAGE, lane, wm, wn, acc);
        if (i + 2 < NC)
            stage_load<BN, TRANSB>(A, Bm, N, K, lda, m0, n0, (i + 2) * 32,
                                   sb + ((i + 2) % NSTAGE) * STAGE, tid);
        cp_commit();
    }
    asm volatile("cp.async.wait_group 0;" ::: "memory");

    // ---------------- epilogue ---------------------------------------------
    const float lsv = (mode == MODE_LS) ? __expf(lsp[0]) : 1.f;
    // warp-uniform group/side for QKV amax tracking
    const int  gW = (n0 + wn * 32) >> 10;
    const bool qsideW = (m0 + wm * 64) < Bq;
    const bool trk = (gW == 0 && qsideW) || (gW == 1 && !qsideW);
    float lm = 0.f;

#pragma unroll
    for (int tm = 0; tm < 4; ++tm) {
#pragma unroll
        for (int tn = 0; tn < 4; ++tn) {
            const int r0 = m0 + wm * 64 + tm * 16 + (lane >> 2);
            const int c0 = n0 + wn * 32 + tn * 8 + 2 * (lane & 3);
#pragma unroll
            for (int h = 0; h < 2; ++h) {
                const int row = r0 + 8 * h;
                const float f0 = acc[tm][tn][2 * h];
                const float f1 = acc[tm][tn][2 * h + 1];
                if (mode == MODE_SMUL) {
                    __nv_bfloat162 p = __floats2bfloat162_rn(f0 * scale, f1 * scale);
                    *reinterpret_cast<__nv_bfloat162*>(
                        (bf16*)Cout + (size_t)row * N + c0) = p;
                } else if (mode == MODE_BNRELU) {
                    float x0 = f0 + bias[c0];
                    x0 = (x0 - mean[c0]) * rsqrtf(var[c0] + 1e-5f) * gam[c0] + bet[c0];
                    float x1 = f1 + bias[c0 + 1];
                    x1 = (x1 - mean[c0 + 1]) * rsqrtf(var[c0 + 1] + 1e-5f) * gam[c0 + 1]
                         + bet[c0 + 1];
                    __nv_bfloat162 p = __floats2bfloat162_rn(fmaxf(x0, 0.f),
                                                             fmaxf(x1, 0.f));
                    *reinterpret_cast<__nv_bfloat162*>(
                        (bf16*)Cout + (size_t)row * N + c0) = p;
                } else if (mode == MODE_QKV) {
                    const int g = c0 >> 10;
                    const int d = c0 & 1023;
                    const float hv0 = f0 + bias[3 * d + g];
                    const float hv1 = f1 + bias[3 * (d + 1) + g];
                    const __nv_bfloat162 p = __floats2bfloat162_rn(hv0, hv1);
                    if (trk) lm = fmaxf(lm, fmaxf(fabsf(hv0), fabsf(hv1)));
                    if (g == 0) {
                        if (row < Bq)
                            *reinterpret_cast<__nv_bfloat162*>(
                                qo + (size_t)row * 1024 + d) = p;
                    } else if (row >= Bq) {
                        bf16* dst = (g == 1) ? ko : vo;
                        *reinterpret_cast<__nv_bfloat162*>(
                            dst + (size_t)(row - Bq) * 1024 + d) = p;
                    }
                } else if (mode == MODE_RESID) {
                    float* Cf = (float*)Cout + (size_t)row * N + c0;
                    const float2 rv = *reinterpret_cast<const float2*>(
                        resid + (size_t)(row & (Bq - 1)) * N + c0);
                    float2 o;
                    o.x = f0 + bias[c0] + rv.x;
                    o.y = f1 + bias[c0 + 1] + rv.y;
                    *reinterpret_cast<float2*>(Cf) = o;
                } else { // MODE_LS
                    if (c0 < N) {
                        float* Cf = (float*)Cout + (size_t)row * N + c0;
                        Cf[0] = f0 * lsv;
                        Cf[1] = f1 * lsv;
                    }
                }
            }
        }
    }

    if (mode == MODE_QKV && amaxp && trk) {
#pragma unroll
        for (int o = 16; o > 0; o >>= 1)
            lm = fmaxf(lm, __shfl_xor_sync(0xffffffffu, lm, o));
        if (lane == 0) {
            if (gW == 0) atomicMax(amaxp + 0, __float_as_uint(lm));
            else         atomicMax(amaxp + 1, __float_as_uint(lm));
        }
    }
}

#define SMEM_NT128 (NSTAGE * (ATILE_B + 128 * SROW))           // 61440
#define SMEM_NT256 (NSTAGE * (ATILE_B + 256 * SROW))           // 92160
#define SMEM_NN256 (NSTAGE * (ATILE_B + 32 * (2 * 256 + 16)))  // 81408

// ---------------- s8 IMMA GEMM: S = sc * Q8 @ K8^T (NT, BN=256) -------------
#define S8_STAGE (ATILE_B + 256 * SROW)          // 30720
#define SMEM_S8  (NSTAGE * S8_STAGE)             // 92160

__global__ __launch_bounds__(512)
void s8_gemm(const int8_t* __restrict__ A, const int8_t* __restrict__ Bm,
             int M, int N, int K, float scale,
             const unsigned* __restrict__ amax, bf16* __restrict__ C)
{
    extern __shared__ char smem[];
    const uint32_t sb = s2u(smem);
    const int tid  = threadIdx.x;
    const int lane = tid & 31;
    const int wid  = tid >> 5;
    const int wm = wid >> 3, wn = wid & 7;
    const int m0 = blockIdx.y * 128;
    const int n0 = blockIdx.x * 256;
    const int NC = K >> 6;                       // k64 per stage

    int acc[4][4][4];
#pragma unroll
    for (int a = 0; a < 4; ++a)
#pragma unroll
        for (int b = 0; b < 4; ++b)
#pragma unroll
            for (int c = 0; c < 4; ++c) acc[a][b][c] = 0;

    // stage loader: A 128 rows x 64B, B 256 rows x 64B (rows always valid)
#pragma unroll
    for (int s = 0; s < 2; ++s) {
        const uint32_t sbase = sb + s * S8_STAGE;
        const int k0 = s * 64;
#pragma unroll
        for (int i = tid; i < 512; i += 512) {
            const int row = i >> 2, ch = i & 3;
            cp16(sbase + row * SROW + ch * 16,
                 A + (size_t)(m0 + row) * K + k0 + ch * 16);
        }
#pragma unroll
        for (int i = tid; i < 1024; i += 512) {
            const int row = i >> 2, ch = i & 3;
            cp16(sbase + ATILE_B + row * SROW + ch * 16,
                 Bm + (size_t)(n0 + row) * K + k0 + ch * 16);
        }
        cp_commit();
    }

    const uint32_t aB0 = (wm * 64 + (lane & 15)) * SROW + (lane >> 4) * 16;
    const uint32_t bB0 = ATILE_B +
                         (wn * 32 + ((lane >> 4) << 3) + (lane & 7)) * SROW +
                         (((lane >> 3) & 1) << 4);

    for (int i = 0; i < NC; ++i) {
        asm volatile("cp.async.wait_group 1;" ::: "memory");
        __syncthreads();
        {
            const uint32_t sbase = sb + (i % NSTAGE) * S8_STAGE;
            const uint32_t aBase = sbase + aB0;
            const uint32_t bBase = sbase + bB0;
#pragma unroll
            for (int kh = 0; kh < 2; ++kh) {
                uint32_t af[4][4];
#pragma unroll
                for (int tm = 0; tm < 4; ++tm)
                    ldmx4(af[tm], aBase + tm * 16 * SROW + kh * 32);
                uint32_t bfr[4][2];
#pragma unroll
                for (int tp = 0; tp < 2; ++tp) {
                    uint32_t r[4];
                    ldmx4(r, bBase + tp * 16 * SROW + kh * 32);
                    bfr[2 * tp][0] = r[0];  bfr[2 * tp][1] = r[1];
                    bfr[2 * tp + 1][0] = r[2]; bfr[2 * tp + 1][1] = r[3];
                }
#pragma unroll
                for (int tm = 0; tm < 4; ++tm)
#pragma unroll
                    for (int tn = 0; tn < 4; ++tn)
                        mma16832s(acc[tm][tn], af[tm], bfr[tn]);
            }
        }
        if (i + 2 < NC) {
            const uint32_t sbase = sb + ((i + 2) % NSTAGE) * S8_STAGE;
            const int k0 = (i + 2) * 64;
#pragma unroll
            for (int j = tid; j < 512; j += 512) {
                const int row = j >> 2, ch = j & 3;
                cp16(sbase + row * SROW + ch * 16,
                     A + (size_t)(m0 + row) * K + k0 + ch * 16);
            }
#pragma unroll
            for (int j = tid; j < 1024; j += 512) {
                const int row = j >> 2, ch = j & 3;
                cp16(sbase + ATILE_B + row * SROW + ch * 16,
                     Bm + (size_t)(n0 + row) * K + k0 + ch * 16);
            }
        }
        cp_commit();
    }
    asm volatile("cp.async.wait_group 0;" ::: "memory");

    const float a0 = fmaxf(__uint_as_float(amax[0]), 1e-20f);
    const float a1 = fmaxf(__uint_as_float(amax[1]), 1e-20f);
    const float sc = scale * (a0 / 127.f) * (a1 / 127.f);

#pragma unroll
    for (int tm = 0; tm < 4; ++tm) {
#pragma unroll
        for (int tn = 0; tn < 4; ++tn) {
            const int r0 = m0 + wm * 64 + tm * 16 + (lane >> 2);
            const int c0 = n0 + wn * 32 + tn * 8 + 2 * (lane & 3);
#pragma unroll
            for (int h = 0; h < 2; ++h) {
                const int row = r0 + 8 * h;
                __nv_bfloat162 p = __floats2bfloat162_rn(
                    (float)acc[tm][tn][2 * h] * sc,
                    (float)acc[tm][tn][2 * h + 1] * sc);
                *reinterpret_cast<__nv_bfloat162*>(
                    C + (size_t)row * N + c0) = p;
            }
        }
    }
}

// ---------------- small kernels --------------------------------------------
// One-shot conversion: inputs -> xb, weights -> bf16 (W3 row-permuted)
__global__ void cvt_all_kernel(const float* __restrict__ Fv,
                               const float* __restrict__ Fvs,
                               const float* __restrict__ Fvt,
                               const float* __restrict__ W1,
                               const float* __restrict__ W2,
                               const float* __restrict__ Wp,
                               const float* __restrict__ W3,
                               bf16* __restrict__ xb, bf16* __restrict__ W1b,
                               bf16* __restrict__ W2b, bf16* __restrict__ Wpb,
                               bf16* __restrict__ W3b)
{
    const int nXB = Mall * Dq;       // 20971520
    const int nW1 = Pq * Dq;         // 131072
    const int nW2 = Pq * Pq;         // 16384
    const int nWp = Dq * Dq;         // 1048576
    const int nW3 = 3 * Dq * Pq;     // 393216
    int i = (blockIdx.x * blockDim.x + threadIdx.x) * 4;
    const float* src;
    bf16* dst;
    if (i < nXB) {
        if (i < Bq * Dq)                  { src = Fv + i;  }
        else if (i < (Bq + Nq) * Dq)      { src = Fvs + (i - Bq * Dq); }
        else                              { src = Fvt + (i - (Bq + Nq) * Dq); }
        dst = xb + i;
    } else if ((i -= nXB) < nW1)          { src = W1 + i; dst = W1b + i; }
    else if ((i -= nW1) < nW2)            { src = W2 + i; dst = W2b + i; }
    else if ((i -= nW2) < nWp)            { src = Wp + i; dst = Wpb + i; }
    else if ((i -= nWp) < nW3) {
        // permuted: out row g*1024+d = orig row 3d+g; 4 cols contiguous
        const int rp = i >> 7, c = i & 127;
        const int g = rp >> 10, d = rp & 1023;
        src = W3 + (3 * d + g) * 128 + c;
        dst = W3b + i;
    } else return;
    const float4 v = *reinterpret_cast<const float4*>(src);
    __nv_bfloat162 a = __floats2bfloat162_rn(v.x, v.y);
    __nv_bfloat162 b = __floats2bfloat162_rn(v.z, v.w);
    uint2 pk;
    pk.x = *reinterpret_cast<uint32_t*>(&a);
    pk.y = *reinterpret_cast<uint32_t*>(&b);
    *reinterpret_cast<uint2*>(dst) = pk;
}

// quantize Q and Kall to int8 using amax scales
__global__ void cvt_s8_kernel(const bf16* __restrict__ Q, const bf16* __restrict__ Kb,
                              int8_t* __restrict__ Q8, int8_t* __restrict__ K8,
                              const unsigned* __restrict__ amax)
{
    const int nQ = Bq * Dq;
    const int nK = 2 * Nq * Dq;
    int i = (blockIdx.x * blockDim.x + threadIdx.x) * 4;
    if (i >= nQ + nK) return;
    const bf16* src;
    int8_t* dst;
    float s;
    if (i < nQ) {
        src = Q + i; dst = Q8 + i;
        s = 127.f / fmaxf(__uint_as_float(amax[0]), 1e-20f);
    } else {
        i -= nQ;
        src = Kb + i; dst = K8 + i;
        s = 127.f / fmaxf(__uint_as_float(amax[1]), 1e-20f);
    }
    const uint2 raw = *reinterpret_cast<const uint2*>(src);
    const float2 f0 = __bfloat1622float2(*reinterpret_cast<const __nv_bfloat162*>(&raw.x));
    const float2 f1 = __bfloat1622float2(*reinterpret_cast<const __nv_bfloat162*>(&raw.y));
    int q0 = __float2int_rn(fminf(fmaxf(f0.x * s, -127.f), 127.f));
    int q1 = __float2int_rn(fminf(fmaxf(f0.y * s, -127.f), 127.f));
    int q2 = __float2int_rn(fminf(fmaxf(f1.x * s, -127.f), 127.f));
    int q3 = __float2int_rn(fminf(fmaxf(f1.y * s, -127.f), 127.f));
    const unsigned pk = (unsigned)(q0 & 0xFF) | ((unsigned)(q1 & 0xFF) << 8) |
                        ((unsigned)(q2 & 0xFF) << 16) | ((unsigned)(q3 & 0xFF) << 24);
    *reinterpret_cast<unsigned*>(dst) = pk;
}

// in-place row softmax over 8192 bf16 cols; row stride 16384, y = bank
__global__ void softmax_bf16(bf16* __restrict__ S)
{
    bf16* p = S + (size_t)blockIdx.x * 16384 + (size_t)blockIdx.y * 8192;
    const int tid = threadIdx.x;
    const int lane = tid & 31, w = tid >> 5;

    float v[32];
    float mx = -3.4e38f;
#pragma unroll
    for (int i = 0; i < 16; ++i) {
        const __nv_bfloat162 h2 = *reinterpret_cast<const __nv_bfloat162*>(
            p + tid * 2 + (i << 9));
        const float2 f2 = __bfloat1622float2(h2);
        v[2 * i] = f2.x; v[2 * i + 1] = f2.y;
        mx = fmaxf(mx, fmaxf(f2.x, f2.y));
    }
    __shared__ float shm[8], shs[8];
#pragma unroll
    for (int o = 16; o > 0; o >>= 1) mx = fmaxf(mx, __shfl_xor_sync(0xffffffffu, mx, o));
    if (lane == 0) shm[w] = mx;
    __syncthreads();
    if (tid == 0) {
        float m = shm[0];
#pragma unroll
        for (int i = 1; i < 8; ++i) m = fmaxf(m, shm[i]);
        shm[0] = m;
    }
    __syncthreads();
    mx = shm[0];

    float s = 0.f;
#pragma unroll
    for (int i = 0; i < 32; ++i) { v[i] = __expf(v[i] - mx); s += v[i]; }
#pragma unroll
    for (int o = 16; o > 0; o >>= 1) s += __shfl_xor_sync(0xffffffffu, s, o);
    if (lane == 0) shs[w] = s;
    __syncthreads();
    if (tid == 0) {
        float t = 0.f;
#pragma unroll
        for (int i = 0; i < 8; ++i) t += shs[i];
        shs[0] = t;
    }
    __syncthreads();
    const float inv = 1.f / shs[0];
#pragma unroll
    for (int i = 0; i < 16; ++i) {
        const __nv_bfloat162 h2 = __floats2bfloat162_rn(v[2 * i] * inv,
                                                        v[2 * i + 1] * inv);
        *reinterpret_cast<__nv_bfloat162*>(p + tid * 2 + (i << 9)) = h2;
    }
}

// G[r] = F[r]/||F[r]|| + F[r+4096]/||F[r+4096]||
__global__ void norm2_acc_kernel(const float* __restrict__ F, float* __restrict__ G)
{
    const float* p0 = F + (size_t)blockIdx.x * 1024;
    const float* p1 = p0 + (size_t)Bq * 1024;
    float* q = G + (size_t)blockIdx.x * 1024;
    const int tid = threadIdx.x;
    const int lane = tid & 31, w = tid >> 5;

    const float4 v0 = *reinterpret_cast<const float4*>(p0 + tid * 4);
    const float4 v1 = *reinterpret_cast<const float4*>(p1 + tid * 4);
    float s0 = v0.x * v0.x + v0.y * v0.y + v0.z * v0.z + v0.w * v0.w;
    float s1 = v1.x * v1.x + v1.y * v1.y + v1.z * v1.z + v1.w * v1.w;
#pragma unroll
    for (int o = 16; o > 0; o >>= 1) {
        s0 += __shfl_xor_sync(0xffffffffu, s0, o);
        s1 += __shfl_xor_sync(0xffffffffu, s1, o);
    }
    __shared__ float sh0[8], sh1[8];
    if (lane == 0) { sh0[w] = s0; sh1[w] = s1; }
    __syncthreads();
    if (tid == 0) {
        float t0 = 0.f, t1 = 0.f;
#pragma unroll
        for (int i = 0; i < 8; ++i) { t0 += sh0[i]; t1 += sh1[i]; }
        sh0[0] = t0; sh1[0] = t1;
    }
    __syncthreads();
    const float rn0 = rsqrtf(sh0[0]);
    const float rn1 = rsqrtf(sh1[0]);

    float4 o;
    o.x = v0.x * rn0 + v1.x * rn1;
    o.y = v0.y * rn0 + v1.y * rn1;
    o.z = v0.z * rn0 + v1.z * rn1;
    o.w = v0.w * rn0 + v1.w * rn1;
    *reinterpret_cast<float4*>(q + tid * 4) = o;
}

// A' = [Gh | Gh | Gl]
__global__ void build_Ap_kernel(const float* __restrict__ G, bf16* __restrict__ Ap)
{
    const int idx = blockIdx.x * blockDim.x + threadIdx.x;
    if (idx >= Bq * Dq) return;
    const int r = idx >> 10, c = idx & 1023;
    const float v = G[idx];
    const bf16 h = __float2bfloat16(v);
    const bf16 l = __float2bfloat16(v - __bfloat162float(h));
    bf16* row = Ap + (size_t)r * 3072;
    row[c] = h; row[1024 + c] = h; row[2048 + c] = l;
}

// B' = [Fh | Fl | Fh]
__global__ void build_Bp_kernel(const float* __restrict__ Ft, bf16* __restrict__ Bp)
{
    const int idx = blockIdx.x * blockDim.x + threadIdx.x;
    if (idx >= Cq * Dq) return;
    const int r = idx >> 10, c = idx & 1023;
    const float v = Ft[idx];
    const bf16 h = __float2bfloat16(v);
    const bf16 l = __float2bfloat16(v - __bfloat162float(h));
    bf16* row = Bp + (size_t)r * 3072;
    row[c] = h; row[1024 + c] = l; row[2048 + c] = h;
}

// ---------------- host side ------------------------------------------------
struct GemmArgs {
    const float *bias = nullptr, *gam = nullptr, *bet = nullptr;
    const float *mean = nullptr, *var = nullptr, *resid = nullptr, *lsp = nullptr;
    bf16 *qo = nullptr, *ko = nullptr, *vo = nullptr;
    unsigned* amaxp = nullptr;
    int lda = 0;
    size_t aOff = 0, bOff = 0, cOffB = 0;
    int gz = 1;
};

static void tc(bool transB, const bf16* A, const bf16* B, int M, int N, int K,
               int mode, float scale, void* C, const GemmArgs& g)
{
    const int lda = g.lda ? g.lda : K;
    if (!transB) {
        dim3 grid(N / 256, M / 128, g.gz);
        tc_gemm<256, false><<<grid, 512, SMEM_NN256>>>(A, B, M, N, K, lda,
            g.aOff, g.bOff, g.cOffB, mode, scale, g.bias, g.gam, g.bet,
            g.mean, g.var, g.resid, g.lsp, C, g.qo, g.ko, g.vo, g.amaxp);
    } else if (N >= 256) {
        dim3 grid((N + 255) / 256, M / 128, g.gz);
        tc_gemm<256, true><<<grid, 512, SMEM_NT256>>>(A, B, M, N, K, lda,
            g.aOff, g.bOff, g.cOffB, mode, scale, g.bias, g.gam, g.bet,
            g.mean, g.var, g.resid, g.lsp, C, g.qo, g.ko, g.vo, g.amaxp);
    } else {
        dim3 grid((N + 127) / 128, M / 128, g.gz);
        tc_gemm<128, true><<<grid, 256, SMEM_NT128>>>(A, B, M, N, K, lda,
            g.aOff, g.bOff, g.cOffB, mode, scale, g.bias, g.gam, g.bet,
            g.mean, g.var, g.resid, g.lsp, C, g.qo, g.ko, g.vo, g.amaxp);
    }
}

extern "C" void kernel_launch(void* const* d_in, const int* in_sizes, int n_in,
                              void* d_out, int out_size)
{
    (void)in_sizes; (void)n_in; (void)out_size;
    const float* Ft  = (const float*)d_in[0];
    const float* Fv  = (const float*)d_in[1];
    const float* Fvs = (const float*)d_in[2];
    const float* Fvt = (const float*)d_in[3];
    const float* W1  = (const float*)d_in[4];
    const float* b1  = (const float*)d_in[5];
    const float* g1  = (const float*)d_in[6];
    const float* be1 = (const float*)d_in[7];
    const float* m1  = (const float*)d_in[8];
    const float* v1  = (const float*)d_in[9];
    const float* W2  = (const float*)d_in[10];
    const float* b2  = (const float*)d_in[11];
    const float* g2  = (const float*)d_in[12];
    const float* be2 = (const float*)d_in[13];
    const float* m2  = (const float*)d_in[14];
    const float* v2  = (const float*)d_in[15];
    const float* W3  = (const float*)d_in[16];
    const float* b3  = (const float*)d_in[17];
    const float* Wp  = (const float*)d_in[18];
    const float* bp  = (const float*)d_in[19];
    const float* ls  = (const float*)d_in[20];
    float* out = (float*)d_out;

    cudaFuncSetAttribute((const void*)tc_gemm<128, true>,
                         cudaFuncAttributeMaxDynamicSharedMemorySize, SMEM_NT128);
    cudaFuncSetAttribute((const void*)tc_gemm<256, true>,
                         cudaFuncAttributeMaxDynamicSharedMemorySize, SMEM_NT256);
    cudaFuncSetAttribute((const void*)tc_gemm<256, false>,
                         cudaFuncAttributeMaxDynamicSharedMemorySize, SMEM_NN256);
    cudaFuncSetAttribute((const void*)s8_gemm,
                         cudaFuncAttributeMaxDynamicSharedMemorySize, SMEM_S8);

    bf16 *xb, *W1b, *W2b, *W3b, *Wpb, *H1b, *H2b, *Qb, *Kall, *Vall, *Sall, *AVal, *Ap, *Bp;
    float *F, *G;
    int8_t *Q8, *K8;
    unsigned* amax;
    cudaGetSymbolAddress((void**)&xb,   g_xb);
    cudaGetSymbolAddress((void**)&W1b,  g_W1b);
    cudaGetSymbolAddress((void**)&W2b,  g_W2b);
    cudaGetSymbolAddress((void**)&W3b,  g_W3b);
    cudaGetSymbolAddress((void**)&Wpb,  g_Wpb);
    cudaGetSymbolAddress((void**)&H1b,  g_H1b);
    cudaGetSymbolAddress((void**)&H2b,  g_H2b);
    cudaGetSymbolAddress((void**)&Qb,   g_Qb);
    cudaGetSymbolAddress((void**)&Kall, g_Kall);
    cudaGetSymbolAddress((void**)&Vall, g_Vall);
    cudaGetSymbolAddress((void**)&Sall, g_Sall);
    cudaGetSymbolAddress((void**)&AVal, g_AVal);
    cudaGetSymbolAddress((void**)&F,    g_F);
    cudaGetSymbolAddress((void**)&G,    g_G);
    cudaGetSymbolAddress((void**)&Ap,   g_Ap);
    cudaGetSymbolAddress((void**)&Bp,   g_Bp);
    cudaGetSymbolAddress((void**)&Q8,   g_Q8);
    cudaGetSymbolAddress((void**)&K8,   g_K8);
    cudaGetSymbolAddress((void**)&amax, g_amax);

    // launch 0: all conversions (inputs + weights, W3 permuted)
    {
        const int total = Mall * Dq + Pq * Dq + Pq * Pq + Dq * Dq + 3 * Dq * Pq;
        cvt_all_kernel<<<(total / 4 + 255) / 256, 256>>>(
            Fv, Fvs, Fvt, W1, W2, Wp, W3, xb, W1b, W2b, Wpb, W3b);
    }
    cudaMemsetAsync(amax, 0, 2 * sizeof(unsigned));

    // launches 1-3: batched pre_project (rows = [Fv; Fvs; Fvt])
    {
        GemmArgs a; a.bias = b1; a.gam = g1; a.bet = be1; a.mean = m1; a.var = v1;
        tc(true, xb, W1b, Mall, Pq, Dq, MODE_BNRELU, 1.f, H1b, a);
    }
    {
        GemmArgs a; a.bias = b2; a.gam = g2; a.bet = be2; a.mean = m2; a.var = v2;
        tc(true, H1b, W2b, Mall, Pq, Pq, MODE_BNRELU, 1.f, H2b, a);
    }
    {
        GemmArgs a; a.bias = b3; a.qo = Qb; a.ko = Kall; a.vo = Vall; a.amaxp = amax;
        tc(true, H2b, W3b, Mall, 3 * Dq, Pq, MODE_QKV, 1.f, nullptr, a);
    }

    // launch 4: quantize Q, Kall to int8
    {
        const int total = Bq * Dq + 2 * Nq * Dq;
        cvt_s8_kernel<<<(total / 4 + 255) / 256, 256>>>(Qb, Kall, Q8, K8, amax);
    }

    // launch 5: S_all = 0.1 * Q8 @ K8^T  (int8 IMMA) — ncu capture target
    {
        dim3 grid(2 * Nq / 256, Bq / 128);
        s8_gemm<<<grid, 512, SMEM_S8>>>(Q8, K8, Bq, 2 * Nq, Dq, 0.1f, amax, Sall);
    }
    softmax_bf16<<<dim3(Bq, 2), 256>>>(Sall);

    // AV_z = S_z @ V_z (z-batched NN, bf16)
    {
        GemmArgs a;
        a.lda = 2 * Nq;
        a.aOff = (size_t)Nq;
        a.bOff = (size_t)Nq * Dq;
        a.cOffB = (size_t)Bq * Dq * sizeof(bf16);
        a.gz = 2;
        tc(false, Sall, Vall, Bq, Dq, Nq, MODE_SMUL, 1.f, AVal, a);
    }

    // F = Fv + AV @ Wp^T + bp  (both banks, fp32)
    {
        GemmArgs a; a.bias = bp; a.resid = Fv;
        tc(true, AVal, Wpb, 2 * Bq, Dq, Dq, MODE_RESID, 1.f, F, a);
    }

    norm2_acc_kernel<<<Bq, 256>>>(F, G);

    // logits = exp(ls) * G @ Ft^T via bf16 split (3-term)
    build_Ap_kernel<<<(Bq * Dq + 255) / 256, 256>>>(G, Ap);
    build_Bp_kernel<<<(Cq * Dq + 255) / 256, 256>>>(Ft, Bp);
    {
        GemmArgs a; a.lsp = ls;
        tc(true, Ap, Bp, Bq, Cq, 3 * Dq, MODE_LS, 1.f, out, a);
    }
}

// round 14
// speedup vs baseline: 2.7919x; 2.7919x over previous
#include <cuda_runtime.h>
#include <cuda_bf16.h>
#include <math.h>
#include <stdint.h>

typedef __nv_bfloat16 bf16;

#define Dq 1024
#define Pq 128
#define Bq 4096
#define Nq 8192
#define Cq 1000
#define Mall 20480              // 4096 + 2*8192

// ---------------- scratch (static device memory; no allocations) -----------
__device__ bf16  g_xb  [(size_t)Mall * Dq];
__device__ bf16  g_W1b [Pq * Dq];
__device__ bf16  g_W2b [Pq * Pq];
__device__ bf16  g_Wpb [Dq * Dq];
__device__ bf16  g_W3T [3 * Pq * Dq];        // [g][j][d] = W3[(3d+g)*128 + j]
__device__ bf16  g_H1b [(size_t)Mall * Pq];
__device__ bf16  g_H2b [(size_t)Mall * Pq];
__device__ bf16  g_Mt  [Pq * Pq];            // Mt[j][i] = (W3q^T W3k)[i][j]
__device__ float g_vb  [Pq];                 // v[j] = b3q^T W3k[:,j]
__device__ bf16  g_Wvp [Dq * Pq];            // Wp @ W3v
__device__ bf16  g_Wvp2[Dq * 2 * Pq];        // [Wvp | Wvp]
__device__ float g_bv2 [Dq];                 // Wp b3v + bp
__device__ bf16  g_T   [Bq * Pq];
__device__ bf16  g_Sall[(size_t)Bq * 2 * Nq];
__device__ bf16  g_Ucat[(size_t)2 * Bq * 2 * Pq];  // per bank: 4096 x 256
__device__ float g_F   [(size_t)2 * Bq * Dq];
__device__ float g_G   [Bq * Dq];
__device__ bf16  g_Ap  [(size_t)Bq * 3 * Dq];
__device__ bf16  g_Bp  [(size_t)Cq * 3 * Dq];

// ---------------- helpers ---------------------------------------------------
__device__ __forceinline__ uint32_t s2u(const void* p) {
    uint32_t a;
    asm("{ .reg .u64 t; cvta.to.shared.u64 t, %1; cvt.u32.u64 %0, t; }"
        : "=r"(a) : "l"(p));
    return a;
}
__device__ __forceinline__ void ldmx4(uint32_t* r, uint32_t a) {
    asm volatile("ldmatrix.sync.aligned.m8n8.x4.shared.b16 {%0,%1,%2,%3}, [%4];"
                 : "=r"(r[0]), "=r"(r[1]), "=r"(r[2]), "=r"(r[3]) : "r"(a));
}
__device__ __forceinline__ void ldmx4t(uint32_t* r, uint32_t a) {
    asm volatile("ldmatrix.sync.aligned.m8n8.x4.trans.shared.b16 {%0,%1,%2,%3}, [%4];"
                 : "=r"(r[0]), "=r"(r[1]), "=r"(r[2]), "=r"(r[3]) : "r"(a));
}
__device__ __forceinline__ void mma16816(float* c, const uint32_t* a, const uint32_t* b) {
    asm volatile("mma.sync.aligned.m16n8k16.row.col.f32.bf16.bf16.f32 "
                 "{%0,%1,%2,%3}, {%4,%5,%6,%7}, {%8,%9}, {%0,%1,%2,%3};"
                 : "+f"(c[0]), "+f"(c[1]), "+f"(c[2]), "+f"(c[3])
                 : "r"(a[0]), "r"(a[1]), "r"(a[2]), "r"(a[3]),
                   "r"(b[0]), "r"(b[1]));
}
__device__ __forceinline__ void cp16(uint32_t dst, const void* src) {
    asm volatile("cp.async.cg.shared.global [%0], [%1], 16;"
                 :: "r"(dst), "l"(src));
}
__device__ __forceinline__ void cp16z(uint32_t dst, const void* src, int sz) {
    asm volatile("cp.async.cg.shared.global [%0], [%1], 16, %2;"
                 :: "r"(dst), "l"(src), "r"(sz));
}
__device__ __forceinline__ void cp_commit() {
    asm volatile("cp.async.commit_group;" ::: "memory");
}

// ---------------- mma.sync GEMM ---------------------------------------------
// TRANSB=true : C(MxN) = A(MxK) @ B(NxK)^T ; TRANSB=false: B is (KxN)
// BM=128, BN in {128,256}, BK=32, 2*BN threads, warp tile 64x32,
// 3-stage cp.async. z decodes (bank, part): part = z % kparts, bank = z / kparts.
#define SROW 80
#define ATILE_B (128 * SROW)           // 10240
#define NSTAGE  3

#define MODE_SMUL   0  // bf16 out = acc*scale
#define MODE_BNRELU 1  // bf16 out = relu(bn(acc+bias))
#define MODE_RESID  3  // f32 out = acc + bias[c] + resid[row&4095,c]
#define MODE_LS     4  // f32 out = acc * exp(*lsp), ragged-N guarded
#define MODE_BIAS   5  // bf16 out = acc + bias[c]

template <int BN, bool TRANSB>
__device__ __forceinline__ void stage_load(const bf16* __restrict__ A,
                                           const bf16* __restrict__ Bm,
                                           int N_, int K_, int lda,
                                           int m0, int n0, int k0,
                                           uint32_t sbase, int tid)
{
    const int T = 2 * BN;
#pragma unroll
    for (int i = tid; i < 512; i += T) {
        const int row = i >> 2, ch = i & 3;
        cp16(sbase + row * SROW + ch * 16,
             A + (size_t)(m0 + row) * lda + k0 + ch * 8);
    }
    if (TRANSB) {
#pragma unroll
        for (int i = tid; i < 4 * BN; i += T) {
            const int row = i >> 2, ch = i & 3;
            const int grow = n0 + row;
            const int v = (grow < N_);
            cp16z(sbase + ATILE_B + row * SROW + ch * 16,
                  Bm + (size_t)(v ? grow : 0) * K_ + k0 + ch * 8, v ? 16 : 0);
        }
    } else {
        constexpr int CPR = BN / 8;
        constexpr int BROW = 2 * BN + 16;
#pragma unroll
        for (int i = tid; i < 32 * CPR; i += T) {
            const int kk = i / CPR, ch = i % CPR;
            cp16(sbase + ATILE_B + kk * BROW + ch * 16,
                 Bm + (size_t)(k0 + kk) * N_ + n0 + ch * 8);
        }
    }
}

template <int BN, bool TRANSB>
__device__ __forceinline__ void compute_stage(uint32_t sbase, int lane,
                                              int wm, int wn,
                                              float acc[4][4][4])
{
    constexpr int BROW = 2 * BN + 16;
    const uint32_t aBase = sbase + (wm * 64 + (lane & 15)) * SROW + (lane >> 4) * 16;
    uint32_t bBase;
    if (TRANSB) {
        bBase = sbase + ATILE_B +
                (wn * 32 + ((lane >> 4) << 3) + (lane & 7)) * SROW +
                (((lane >> 3) & 1) << 4);
    } else {
        bBase = sbase + ATILE_B +
                ((lane & 7) + (((lane >> 3) & 1) << 3)) * BROW +
                (wn * 32 + (lane >> 4) * 8) * 2;
    }
#pragma unroll
    for (int kh = 0; kh < 2; ++kh) {
        uint32_t af[4][4];
#pragma unroll
        for (int tm = 0; tm < 4; ++tm)
            ldmx4(af[tm], aBase + tm * 16 * SROW + kh * 32);
        uint32_t bfr[4][2];
#pragma unroll
        for (int tp = 0; tp < 2; ++tp) {
            uint32_t r[4];
            if (TRANSB) ldmx4(r, bBase + tp * 16 * SROW + kh * 32);
            else        ldmx4t(r, bBase + kh * 16 * BROW + tp * 32);
            bfr[2 * tp][0] = r[0];  bfr[2 * tp][1] = r[1];
            bfr[2 * tp + 1][0] = r[2]; bfr[2 * tp + 1][1] = r[3];
        }
#pragma unroll
        for (int tm = 0; tm < 4; ++tm)
#pragma unroll
            for (int tn = 0; tn < 4; ++tn)
                mma16816(acc[tm][tn], af[tm], bfr[tn]);
    }
}

template <int BN, bool TRANSB>
__global__ __launch_bounds__(2 * BN)
void tc_gemm(const bf16* __restrict__ A, const bf16* __restrict__ Bm,
             int M, int N, int K, int lda, int ldc, int kparts,
             size_t aOff1, size_t bOff1, size_t cOff1B,
             size_t aOff2, size_t bOff2, size_t cOff2B,
             int mode, float scale,
             const float* __restrict__ bias, const float* __restrict__ gam,
             const float* __restrict__ bet, const float* __restrict__ mean,
             const float* __restrict__ var, const float* __restrict__ resid,
             const float* __restrict__ lsp,
             void* __restrict__ Cout)
{
    constexpr int NW = BN / 32;
    constexpr int BSTAGE = TRANSB ? BN * SROW : 32 * (2 * BN + 16);
    constexpr int STAGE = ATILE_B + BSTAGE;
    extern __shared__ char smem[];
    const uint32_t sb = s2u(smem);
    {
        const int z = blockIdx.z;
        const int part = z % kparts, bank = z / kparts;
        A    += bank * aOff2 + part * aOff1;
        Bm   += bank * bOff2 + part * bOff1;
        Cout  = (void*)((char*)Cout + (size_t)bank * cOff2B + (size_t)part * cOff1B);
    }
    const int tid  = threadIdx.x;
    const int lane = tid & 31;
    const int wid  = tid >> 5;
    const int wm = wid / NW, wn = wid % NW;
    const int m0 = blockIdx.y * 128;
    const int n0 = blockIdx.x * BN;
    const int NC = K >> 5;

    float acc[4][4][4];
#pragma unroll
    for (int a = 0; a < 4; ++a)
#pragma unroll
        for (int b = 0; b < 4; ++b)
#pragma unroll
            for (int c = 0; c < 4; ++c) acc[a][b][c] = 0.f;

#pragma unroll
    for (int s = 0; s < 2; ++s) {
        stage_load<BN, TRANSB>(A, Bm, N, K, lda, m0, n0, s * 32, sb + s * STAGE, tid);
        cp_commit();
    }

    for (int i = 0; i < NC; ++i) {
        asm volatile("cp.async.wait_group 1;" ::: "memory");
        __syncthreads();
        compute_stage<BN, TRANSB>(sb + (i % NSTAGE) * STAGE, lane, wm, wn, acc);
        if (i + 2 < NC)
            stage_load<BN, TRANSB>(A, Bm, N, K, lda, m0, n0, (i + 2) * 32,
                                   sb + ((i + 2) % NSTAGE) * STAGE, tid);
        cp_commit();
    }
    asm volatile("cp.async.wait_group 0;" ::: "memory");

    // ---------------- epilogue ---------------------------------------------
    const float lsv = (mode == MODE_LS) ? __expf(lsp[0]) : 1.f;

#pragma unroll
    for (int tm = 0; tm < 4; ++tm) {
#pragma unroll
        for (int tn = 0; tn < 4; ++tn) {
            const int r0 = m0 + wm * 64 + tm * 16 + (lane >> 2);
            const int c0 = n0 + wn * 32 + tn * 8 + 2 * (lane & 3);
#pragma unroll
            for (int h = 0; h < 2; ++h) {
                const int row = r0 + 8 * h;
                const float f0 = acc[tm][tn][2 * h];
                const float f1 = acc[tm][tn][2 * h + 1];
                if (mode == MODE_SMUL) {
                    __nv_bfloat162 p = __floats2bfloat162_rn(f0 * scale, f1 * scale);
                    *reinterpret_cast<__nv_bfloat162*>(
                        (bf16*)Cout + (size_t)row * ldc + c0) = p;
                } else if (mode == MODE_BIAS) {
                    __nv_bfloat162 p = __floats2bfloat162_rn(f0 + bias[c0],
                                                             f1 + bias[c0 + 1]);
                    *reinterpret_cast<__nv_bfloat162*>(
                        (bf16*)Cout + (size_t)row * ldc + c0) = p;
                } else if (mode == MODE_BNRELU) {
                    float x0 = f0 + bias[c0];
                    x0 = (x0 - mean[c0]) * rsqrtf(var[c0] + 1e-5f) * gam[c0] + bet[c0];
                    float x1 = f1 + bias[c0 + 1];
                    x1 = (x1 - mean[c0 + 1]) * rsqrtf(var[c0 + 1] + 1e-5f) * gam[c0 + 1]
                         + bet[c0 + 1];
                    __nv_bfloat162 p = __floats2bfloat162_rn(fmaxf(x0, 0.f),
                                                             fmaxf(x1, 0.f));
                    *reinterpret_cast<__nv_bfloat162*>(
                        (bf16*)Cout + (size_t)row * ldc + c0) = p;
                } else if (mode == MODE_RESID) {
                    float* Cf = (float*)Cout + (size_t)row * ldc + c0;
                    const float2 rv = *reinterpret_cast<const float2*>(
                        resid + (size_t)(row & (Bq - 1)) * ldc + c0);
                    float2 o;
                    o.x = f0 + bias[c0] + rv.x;
                    o.y = f1 + bias[c0 + 1] + rv.y;
                    *reinterpret_cast<float2*>(Cf) = o;
                } else { // MODE_LS (ragged N; N even so pair guard ok)
                    if (c0 < N) {
                        float* Cf = (float*)Cout + (size_t)row * ldc + c0;
                        Cf[0] = f0 * lsv;
                        Cf[1] = f1 * lsv;
                    }
                }
            }
        }
    }
}

#define SMEM_NT128 (NSTAGE * (ATILE_B + 128 * SROW))           // 61440
#define SMEM_NT256 (NSTAGE * (ATILE_B + 256 * SROW))           // 92160
#define SMEM_NN256 (NSTAGE * (ATILE_B + 32 * (2 * 256 + 16)))  // 81408
#define SMEM_NN128 (NSTAGE * (ATILE_B + 32 * (2 * 128 + 16)))  // 56832

// ---------------- small kernels --------------------------------------------
// One-shot conversion: inputs -> xb; W1, W2, Wp -> bf16; W3 -> three
// transposed bf16 blocks W3T[g][j][d] = W3[(3d+g)*128 + j].
__global__ void cvt_all_kernel(const float* __restrict__ Fv,
                               const float* __restrict__ Fvs,
                               const float* __restrict__ Fvt,
                               const float* __restrict__ W1,
                               const float* __restrict__ W2,
                               const float* __restrict__ Wp,
                               const float* __restrict__ W3,
                               bf16* __restrict__ xb, bf16* __restrict__ W1b,
                               bf16* __restrict__ W2b, bf16* __restrict__ Wpb,
                               bf16* __restrict__ W3T)
{
    const int nXB = Mall * Dq;
    const int nW1 = Pq * Dq;
    const int nW2 = Pq * Pq;
    const int nWp = Dq * Dq;
    const int nT1 = Pq * Dq;         // one W3T block
    int i = (blockIdx.x * blockDim.x + threadIdx.x) * 4;
    const float* src = nullptr;
    bf16* dst;
    float f4[4];
    bool gather = false;
    if (i < nXB) {
        if (i < Bq * Dq)                  { src = Fv + i;  }
        else if (i < (Bq + Nq) * Dq)      { src = Fvs + (i - Bq * Dq); }
        else                              { src = Fvt + (i - (Bq + Nq) * Dq); }
        dst = xb + i;
    } else if ((i -= nXB) < nW1)          { src = W1 + i; dst = W1b + i; }
    else if ((i -= nW1) < nW2)            { src = W2 + i; dst = W2b + i; }
    else if ((i -= nW2) < nWp)            { src = Wp + i; dst = Wpb + i; }
    else if ((i -= nWp) < 3 * nT1) {
        const int g = i / nT1;
        const int r = i - g * nT1;
        const int j = r >> 10, d0 = r & 1023;
#pragma unroll
        for (int e = 0; e < 4; ++e)
            f4[e] = W3[(3 * (d0 + e) + g) * 128 + j];
        dst = W3T + i;
        gather = true;
    } else return;
    if (!gather) {
        const float4 v = *reinterpret_cast<const float4*>(src);
        f4[0] = v.x; f4[1] = v.y; f4[2] = v.z; f4[3] = v.w;
    }
    __nv_bfloat162 a = __floats2bfloat162_rn(f4[0], f4[1]);
    __nv_bfloat162 b = __floats2bfloat162_rn(f4[2], f4[3]);
    uint2 pk;
    pk.x = *reinterpret_cast<uint32_t*>(&a);
    pk.y = *reinterpret_cast<uint32_t*>(&b);
    *reinterpret_cast<uint2*>(dst) = pk;
}

// v[j] = sum_d b3[3d] * W3[(3d+1)*128 + j]
__global__ void prep_v_kernel(const float* __restrict__ W3,
                              const float* __restrict__ b3,
                              float* __restrict__ vb)
{
    const int j = threadIdx.x;
    float acc = 0.f;
    for (int d = 0; d < 1024; ++d)
        acc += b3[3 * d] * W3[(3 * d + 1) * 128 + j];
    vb[j] = acc;
}

// bv2[i] = sum_d Wp[i,d]*b3[3d+2] + bp[i]
__global__ void prep_bv2_kernel(const float* __restrict__ Wp,
                                const float* __restrict__ b3,
                                const float* __restrict__ bp,
                                float* __restrict__ bv2)
{
    const int i = blockIdx.x * blockDim.x + threadIdx.x;
    if (i >= Dq) return;
    float acc = 0.f;
    const float* wpr = Wp + (size_t)i * 1024;
    for (int d = 0; d < 1024; ++d)
        acc += wpr[d] * b3[3 * d + 2];
    bv2[i] = acc + bp[i];
}

// Wvp2 = [Wvp | Wvp]
__global__ void dup_wvp_kernel(const bf16* __restrict__ Wvp, bf16* __restrict__ Wvp2)
{
    const int idx = blockIdx.x * blockDim.x + threadIdx.x;
    if (idx >= Dq * Pq) return;
    const int i = idx >> 7, j = idx & 127;
    const bf16 h = Wvp[idx];
    Wvp2[(size_t)i * 256 + j] = h;
    Wvp2[(size_t)i * 256 + 128 + j] = h;
}

// in-place row softmax over 8192 bf16 cols; row stride 16384, y = bank
__global__ void softmax_bf16(bf16* __restrict__ S)
{
    bf16* p = S + (size_t)blockIdx.x * 16384 + (size_t)blockIdx.y * 8192;
    const int tid = threadIdx.x;
    const int lane = tid & 31, w = tid >> 5;

    float v[32];
    float mx = -3.4e38f;
#pragma unroll
    for (int i = 0; i < 16; ++i) {
        const __nv_bfloat162 h2 = *reinterpret_cast<const __nv_bfloat162*>(
            p + tid * 2 + (i << 9));
        const float2 f2 = __bfloat1622float2(h2);
        v[2 * i] = f2.x; v[2 * i + 1] = f2.y;
        mx = fmaxf(mx, fmaxf(f2.x, f2.y));
    }
    __shared__ float shm[8], shs[8];
#pragma unroll
    for (int o = 16; o > 0; o >>= 1) mx = fmaxf(mx, __shfl_xor_sync(0xffffffffu, mx, o));
    if (lane == 0) shm[w] = mx;
    __syncthreads();
    if (tid == 0) {
        float m = shm[0];
#pragma unroll
        for (int i = 1; i < 8; ++i) m = fmaxf(m, shm[i]);
        shm[0] = m;
    }
    __syncthreads();
    mx = shm[0];

    float s = 0.f;
#pragma unroll
    for (int i = 0; i < 32; ++i) { v[i] = __expf(v[i] - mx); s += v[i]; }
#pragma unroll
    for (int o = 16; o > 0; o >>= 1) s += __shfl_xor_sync(0xffffffffu, s, o);
    if (lane == 0) shs[w] = s;
    __syncthreads();
    if (tid == 0) {
        float t = 0.f;
#pragma unroll
        for (int i = 0; i < 8; ++i) t += shs[i];
        shs[0] = t;
    }
    __syncthreads();
    const float inv = 1.f / shs[0];
#pragma unroll
    for (int i = 0; i < 16; ++i) {
        const __nv_bfloat162 h2 = __floats2bfloat162_rn(v[2 * i] * inv,
                                                        v[2 * i + 1] * inv);
        *reinterpret_cast<__nv_bfloat162*>(p + tid * 2 + (i << 9)) = h2;
    }
}

// G[r] = F[r]/||F[r]|| + F[r+4096]/||F[r+4096]||
__global__ void norm2_acc_kernel(const float* __restrict__ F, float* __restrict__ G)
{
    const float* p0 = F + (size_t)blockIdx.x * 1024;
    const float* p1 = p0 + (size_t)Bq * 1024;
    float* q = G + (size_t)blockIdx.x * 1024;
    const int tid = threadIdx.x;
    const int lane = tid & 31, w = tid >> 5;

    const float4 v0 = *reinterpret_cast<const float4*>(p0 + tid * 4);
    const float4 v1 = *reinterpret_cast<const float4*>(p1 + tid * 4);
    float s0 = v0.x * v0.x + v0.y * v0.y + v0.z * v0.z + v0.w * v0.w;
    float s1 = v1.x * v1.x + v1.y * v1.y + v1.z * v1.z + v1.w * v1.w;
#pragma unroll
    for (int o = 16; o > 0; o >>= 1) {
        s0 += __shfl_xor_sync(0xffffffffu, s0, o);
        s1 += __shfl_xor_sync(0xffffffffu, s1, o);
    }
    __shared__ float sh0[8], sh1[8];
    if (lane == 0) { sh0[w] = s0; sh1[w] = s1; }
    __syncthreads();
    if (tid == 0) {
        float t0 = 0.f, t1 = 0.f;
#pragma unroll
        for (int i = 0; i < 8; ++i) { t0 += sh0[i]; t1 += sh1[i]; }
        sh0[0] = t0; sh1[0] = t1;
    }
    __syncthreads();
    const float rn0 = rsqrtf(sh0[0]);
    const float rn1 = rsqrtf(sh1[0]);

    float4 o;
    o.x = v0.x * rn0 + v1.x * rn1;
    o.y = v0.y * rn0 + v1.y * rn1;
    o.z = v0.z * rn0 + v1.z * rn1;
    o.w = v0.w * rn0 + v1.w * rn1;
    *reinterpret_cast<float4*>(q + tid * 4) = o;
}

// A' = [Gh | Gh | Gl]
__global__ void build_Ap_kernel(const float* __restrict__ G, bf16* __restrict__ Ap)
{
    const int idx = blockIdx.x * blockDim.x + threadIdx.x;
    if (idx >= Bq * Dq) return;
    const int r = idx >> 10, c = idx & 1023;
    const float v = G[idx];
    const bf16 h = __float2bfloat16(v);
    const bf16 l = __float2bfloat16(v - __bfloat162float(h));
    bf16* row = Ap + (size_t)r * 3072;
    row[c] = h; row[1024 + c] = h; row[2048 + c] = l;
}

// B' = [Fh | Fl | Fh]
__global__ void build_Bp_kernel(const float* __restrict__ Ft, bf16* __restrict__ Bp)
{
    const int idx = blockIdx.x * blockDim.x + threadIdx.x;
    if (idx >= Cq * Dq) return;
    const int r = idx >> 10, c = idx & 1023;
    const float v = Ft[idx];
    const bf16 h = __float2bfloat16(v);
    const bf16 l = __float2bfloat16(v - __bfloat162float(h));
    bf16* row = Bp + (size_t)r * 3072;
    row[c] = h; row[1024 + c] = l; row[2048 + c] = h;
}

// ---------------- host side ------------------------------------------------
struct GemmArgs {
    const float *bias = nullptr, *gam = nullptr, *bet = nullptr;
    const float *mean = nullptr, *var = nullptr, *resid = nullptr, *lsp = nullptr;
    int lda = 0, ldc = 0;                 // 0 -> K / N
    int kparts = 1, gz = 1;
    size_t aOff1 = 0, bOff1 = 0, cOff1B = 0;
    size_t aOff2 = 0, bOff2 = 0, cOff2B = 0;
};

static void tc(bool transB, const bf16* A, const bf16* B, int M, int N, int K,
               int mode, float scale, void* C, const GemmArgs& g)
{
    const int lda = g.lda ? g.lda : K;
    const int ldc = g.ldc ? g.ldc : N;
    if (!transB) {
        if ((N & 255) == 0) {
            dim3 grid(N / 256, M / 128, g.gz);
            tc_gemm<256, false><<<grid, 512, SMEM_NN256>>>(A, B, M, N, K, lda, ldc,
                g.kparts, g.aOff1, g.bOff1, g.cOff1B, g.aOff2, g.bOff2, g.cOff2B,
                mode, scale, g.bias, g.gam, g.bet, g.mean, g.var, g.resid, g.lsp, C);
        } else {
            dim3 grid(N / 128, M / 128, g.gz);
            tc_gemm<128, false><<<grid, 256, SMEM_NN128>>>(A, B, M, N, K, lda, ldc,
                g.kparts, g.aOff1, g.bOff1, g.cOff1B, g.aOff2, g.bOff2, g.cOff2B,
                mode, scale, g.bias, g.gam, g.bet, g.mean, g.var, g.resid, g.lsp, C);
        }
    } else if (N >= 256) {
        dim3 grid((N + 255) / 256, M / 128, g.gz);
        tc_gemm<256, true><<<grid, 512, SMEM_NT256>>>(A, B, M, N, K, lda, ldc,
            g.kparts, g.aOff1, g.bOff1, g.cOff1B, g.aOff2, g.bOff2, g.cOff2B,
            mode, scale, g.bias, g.gam, g.bet, g.mean, g.var, g.resid, g.lsp, C);
    } else {
        dim3 grid((N + 127) / 128, M / 128, g.gz);
        tc_gemm<128, true><<<grid, 256, SMEM_NT128>>>(A, B, M, N, K, lda, ldc,
            g.kparts, g.aOff1, g.bOff1, g.cOff1B, g.aOff2, g.bOff2, g.cOff2B,
            mode, scale, g.bias, g.gam, g.bet, g.mean, g.var, g.resid, g.lsp, C);
    }
}

extern "C" void kernel_launch(void* const* d_in, const int* in_sizes, int n_in,
                              void* d_out, int out_size)
{
    (void)in_sizes; (void)n_in; (void)out_size;
    const float* Ft  = (const float*)d_in[0];
    const float* Fv  = (const float*)d_in[1];
    const float* Fvs = (const float*)d_in[2];
    const float* Fvt = (const float*)d_in[3];
    const float* W1  = (const float*)d_in[4];
    const float* b1  = (const float*)d_in[5];
    const float* g1  = (const float*)d_in[6];
    const float* be1 = (const float*)d_in[7];
    const float* m1  = (const float*)d_in[8];
    const float* v1  = (const float*)d_in[9];
    const float* W2  = (const float*)d_in[10];
    const float* b2  = (const float*)d_in[11];
    const float* g2  = (const float*)d_in[12];
    const float* be2 = (const float*)d_in[13];
    const float* m2  = (const float*)d_in[14];
    const float* v2  = (const float*)d_in[15];
    const float* W3  = (const float*)d_in[16];
    const float* b3  = (const float*)d_in[17];
    const float* Wp  = (const float*)d_in[18];
    const float* bp  = (const float*)d_in[19];
    const float* ls  = (const float*)d_in[20];
    float* out = (float*)d_out;

    cudaFuncSetAttribute((const void*)tc_gemm<128, true>,
                         cudaFuncAttributeMaxDynamicSharedMemorySize, SMEM_NT128);
    cudaFuncSetAttribute((const void*)tc_gemm<256, true>,
                         cudaFuncAttributeMaxDynamicSharedMemorySize, SMEM_NT256);
    cudaFuncSetAttribute((const void*)tc_gemm<256, false>,
                         cudaFuncAttributeMaxDynamicSharedMemorySize, SMEM_NN256);
    cudaFuncSetAttribute((const void*)tc_gemm<128, false>,
                         cudaFuncAttributeMaxDynamicSharedMemorySize, SMEM_NN128);

    bf16 *xb, *W1b, *W2b, *Wpb, *W3T, *H1b, *H2b, *Mt, *Wvp, *Wvp2, *T, *Sall, *Ucat, *Ap, *Bp;
    float *vb, *bv2, *F, *G;
    cudaGetSymbolAddress((void**)&xb,   g_xb);
    cudaGetSymbolAddress((void**)&W1b,  g_W1b);
    cudaGetSymbolAddress((void**)&W2b,  g_W2b);
    cudaGetSymbolAddress((void**)&Wpb,  g_Wpb);
    cudaGetSymbolAddress((void**)&W3T,  g_W3T);
    cudaGetSymbolAddress((void**)&H1b,  g_H1b);
    cudaGetSymbolAddress((void**)&H2b,  g_H2b);
    cudaGetSymbolAddress((void**)&Mt,   g_Mt);
    cudaGetSymbolAddress((void**)&vb,   g_vb);
    cudaGetSymbolAddress((void**)&Wvp,  g_Wvp);
    cudaGetSymbolAddress((void**)&Wvp2, g_Wvp2);
    cudaGetSymbolAddress((void**)&bv2,  g_bv2);
    cudaGetSymbolAddress((void**)&T,    g_T);
    cudaGetSymbolAddress((void**)&Sall, g_Sall);
    cudaGetSymbolAddress((void**)&Ucat, g_Ucat);
    cudaGetSymbolAddress((void**)&F,    g_F);
    cudaGetSymbolAddress((void**)&G,    g_G);
    cudaGetSymbolAddress((void**)&Ap,   g_Ap);
    cudaGetSymbolAddress((void**)&Bp,   g_Bp);

    // 0: conversions
    {
        const int total = Mall * Dq + Pq * Dq + Pq * Pq + Dq * Dq + 3 * Pq * Dq;
        cvt_all_kernel<<<(total / 4 + 255) / 256, 256>>>(
            Fv, Fvs, Fvt, W1, W2, Wp, W3, xb, W1b, W2b, Wpb, W3T);
    }
    // bias precomputes (zeros in this dataset but exact in general)
    prep_v_kernel<<<1, 128>>>(W3, b3, vb);
    prep_bv2_kernel<<<4, 256>>>(Wp, b3, bp, bv2);

    // Mt = (W3q^T W3k)^T : A = W3kT, B = W3qT  (128x128x1024)
    {
        GemmArgs a;
        tc(true, W3T + Pq * Dq, W3T, Pq, Pq, Dq, MODE_SMUL, 1.f, Mt, a);
    }
    // Wvp = Wp @ W3v : A = Wpb, B = W3vT  (1024x128x1024)
    {
        GemmArgs a;
        tc(true, Wpb, W3T + 2 * Pq * Dq, Dq, Pq, Dq, MODE_SMUL, 1.f, Wvp, a);
    }
    dup_wvp_kernel<<<(Dq * Pq + 255) / 256, 256>>>(Wvp, Wvp2);

    // pre_project (rows = [Fv; Fvs; Fvt]) -> H2
    {
        GemmArgs a; a.bias = b1; a.gam = g1; a.bet = be1; a.mean = m1; a.var = v1;
        tc(true, xb, W1b, Mall, Pq, Dq, MODE_BNRELU, 1.f, H1b, a);
    }
    {
        GemmArgs a; a.bias = b2; a.gam = g2; a.bet = be2; a.mean = m2; a.var = v2;
        tc(true, H1b, W2b, Mall, Pq, Pq, MODE_BNRELU, 1.f, H2b, a);
    }

    // T = H2q @ Mt^T + v   (4096 x 128, K=128)
    {
        GemmArgs a; a.bias = vb;
        tc(true, H2b, Mt, Bq, Pq, Pq, MODE_BIAS, 1.f, T, a);
    }

    // S = 0.1 * T @ H2_banks^T   (4096 x 16384, K=128)
    {
        GemmArgs a;
        tc(true, T, H2b + (size_t)Bq * Pq, Bq, 2 * Nq, Pq, MODE_SMUL, 0.1f, Sall, a);
    }
    softmax_bf16<<<dim3(Bq, 2), 256>>>(Sall);

    // U = A @ G  per (bank, k-part): z = bank*2 + part, K=4096 each
    // Ucat per bank: 4096 x 256 (part p at cols [p*128, p*128+128))
    {
        GemmArgs a;
        a.lda = 2 * Nq;
        a.ldc = 256;
        a.kparts = 2; a.gz = 4;
        a.aOff1 = (size_t)Bq;                       // part: +4096 cols in S
        a.bOff1 = (size_t)Bq * Pq;                  // part: +4096 G rows
        a.cOff1B = 128 * sizeof(bf16);              // part: +128 cols in Ucat
        a.aOff2 = (size_t)Nq;                       // bank: +8192 cols in S
        a.bOff2 = (size_t)Nq * Pq;                  // bank: +8192 G rows
        a.cOff2B = (size_t)Bq * 256 * sizeof(bf16); // bank: next Ucat block
        tc(false, Sall, H2b + (size_t)Bq * Pq, Bq, Pq, Bq, MODE_SMUL, 1.f, Ucat, a);
    }

    // F = Fv + Ucat @ Wvp2^T + bv2   (per bank, K=256)
    {
        GemmArgs a; a.bias = bv2; a.resid = Fv;
        a.gz = 2;
        a.aOff2 = (size_t)Bq * 256;
        a.cOff2B = (size_t)Bq * Dq * sizeof(float);
        tc(true, Ucat, Wvp2, Bq, Dq, 256, MODE_RESID, 1.f, F, a);
    }

    norm2_acc_kernel<<<Bq, 256>>>(F, G);

    // logits = exp(ls) * G @ Ft^T via bf16 split (3-term)
    build_Ap_kernel<<<(Bq * Dq + 255) / 256, 256>>>(G, Ap);
    build_Bp_kernel<<<(Cq * Dq + 255) / 256, 256>>>(Ft, Bp);
    {
        GemmArgs a; a.lsp = ls;
        tc(true, Ap, Bp, Bq, Cq, 3 * Dq, MODE_LS, 1.f, out, a);
    }
}

// round 15
// speedup vs baseline: 3.9498x; 1.4147x over previous
#include <cuda_runtime.h>
#include <cuda_bf16.h>
#include <math.h>
#include <stdint.h>

typedef __nv_bfloat16 bf16;

#define Dq 1024
#define Pq 128
#define Bq 4096
#define Nq 8192
#define Cq 1000
#define Mall 20480              // 4096 + 2*8192

// ---------------- scratch (static device memory; no allocations) -----------
__device__ bf16  g_xb  [(size_t)Mall * Dq];
__device__ bf16  g_W1b [Pq * Dq];
__device__ bf16  g_W2b [Pq * Pq];
__device__ bf16  g_Wpb [Dq * Dq];
__device__ bf16  g_W3T [3 * Pq * Dq];        // [g][j][d] = W3[(3d+g)*128 + j]
__device__ bf16  g_H1b [(size_t)Mall * Pq];
__device__ bf16  g_H2b [(size_t)Mall * Pq];
__device__ bf16  g_Mt  [Pq * Pq];            // Mt[j][i] = (W3q^T W3k)[i][j]
__device__ float g_vb  [Pq];                 // v[j] = b3q^T W3k[:,j]
__device__ bf16  g_Wvp [Dq * Pq];            // Wp @ W3v
__device__ float g_bv2 [Dq];                 // Wp b3v + bp
__device__ bf16  g_T   [Bq * Pq];
__device__ bf16  g_Ucat[(size_t)2 * Bq * Pq];      // per bank: 4096 x 128
__device__ float g_Up  [(size_t)4 * Bq * Pq];      // [split][bank][row][dim]
__device__ float g_Um  [4 * Bq];
__device__ float g_Ul  [4 * Bq];
__device__ float g_MtP [8 * Pq * Pq];
__device__ float g_WvpP[4 * Dq * Pq];
__device__ float g_F   [(size_t)2 * Bq * Dq];
__device__ bf16  g_Ap  [(size_t)Bq * 3 * Dq];
__device__ bf16  g_Bp  [(size_t)Cq * 3 * Dq];

// ---------------- helpers ---------------------------------------------------
__device__ __forceinline__ uint32_t s2u(const void* p) {
    uint32_t a;
    asm("{ .reg .u64 t; cvta.to.shared.u64 t, %1; cvt.u32.u64 %0, t; }"
        : "=r"(a) : "l"(p));
    return a;
}
__device__ __forceinline__ void ldmx4(uint32_t* r, uint32_t a) {
    asm volatile("ldmatrix.sync.aligned.m8n8.x4.shared.b16 {%0,%1,%2,%3}, [%4];"
                 : "=r"(r[0]), "=r"(r[1]), "=r"(r[2]), "=r"(r[3]) : "r"(a));
}
__device__ __forceinline__ void ldmx4t(uint32_t* r, uint32_t a) {
    asm volatile("ldmatrix.sync.aligned.m8n8.x4.trans.shared.b16 {%0,%1,%2,%3}, [%4];"
                 : "=r"(r[0]), "=r"(r[1]), "=r"(r[2]), "=r"(r[3]) : "r"(a));
}
__device__ __forceinline__ void mma16816(float* c, const uint32_t* a, const uint32_t* b) {
    asm volatile("mma.sync.aligned.m16n8k16.row.col.f32.bf16.bf16.f32 "
                 "{%0,%1,%2,%3}, {%4,%5,%6,%7}, {%8,%9}, {%0,%1,%2,%3};"
                 : "+f"(c[0]), "+f"(c[1]), "+f"(c[2]), "+f"(c[3])
                 : "r"(a[0]), "r"(a[1]), "r"(a[2]), "r"(a[3]),
                   "r"(b[0]), "r"(b[1]));
}
__device__ __forceinline__ void cp16(uint32_t dst, const void* src) {
    asm volatile("cp.async.cg.shared.global [%0], [%1], 16;"
                 :: "r"(dst), "l"(src));
}
__device__ __forceinline__ void cp16z(uint32_t dst, const void* src, int sz) {
    asm volatile("cp.async.cg.shared.global [%0], [%1], 16, %2;"
                 :: "r"(dst), "l"(src), "r"(sz));
}
__device__ __forceinline__ void cp_commit() {
    asm volatile("cp.async.commit_group;" ::: "memory");
}
__device__ __forceinline__ uint32_t packbf2(float x, float y) {
    __nv_bfloat162 h = __floats2bfloat162_rn(x, y);
    return *reinterpret_cast<uint32_t*>(&h);
}

// ---------------- mma.sync GEMM ---------------------------------------------
#define SROW 80
#define ATILE_B (128 * SROW)
#define NSTAGE  3

#define MODE_SMUL   0
#define MODE_BNRELU 1
#define MODE_RESID  3
#define MODE_LS     4
#define MODE_BIAS   5
#define MODE_PART   6  // fp32 out (split-K partial)

template <int BN, bool TRANSB>
__device__ __forceinline__ void stage_load(const bf16* __restrict__ A,
                                           const bf16* __restrict__ Bm,
                                           int N_, int K_, int lda, int ldb,
                                           int m0, int n0, int k0,
                                           uint32_t sbase, int tid)
{
    const int T = 2 * BN;
#pragma unroll
    for (int i = tid; i < 512; i += T) {
        const int row = i >> 2, ch = i & 3;
        cp16(sbase + row * SROW + ch * 16,
             A + (size_t)(m0 + row) * lda + k0 + ch * 8);
    }
    if (TRANSB) {
#pragma unroll
        for (int i = tid; i < 4 * BN; i += T) {
            const int row = i >> 2, ch = i & 3;
            const int grow = n0 + row;
            const int v = (grow < N_);
            cp16z(sbase + ATILE_B + row * SROW + ch * 16,
                  Bm + (size_t)(v ? grow : 0) * ldb + k0 + ch * 8, v ? 16 : 0);
        }
    } else {
        constexpr int CPR = BN / 8;
        constexpr int BROW = 2 * BN + 16;
#pragma unroll
        for (int i = tid; i < 32 * CPR; i += T) {
            const int kk = i / CPR, ch = i % CPR;
            cp16(sbase + ATILE_B + kk * BROW + ch * 16,
                 Bm + (size_t)(k0 + kk) * N_ + n0 + ch * 8);
        }
    }
}

template <int BN, bool TRANSB>
__device__ __forceinline__ void compute_stage(uint32_t sbase, int lane,
                                              int wm, int wn,
                                              float acc[4][4][4])
{
    constexpr int BROW = 2 * BN + 16;
    const uint32_t aBase = sbase + (wm * 64 + (lane & 15)) * SROW + (lane >> 4) * 16;
    uint32_t bBase;
    if (TRANSB) {
        bBase = sbase + ATILE_B +
                (wn * 32 + ((lane >> 4) << 3) + (lane & 7)) * SROW +
                (((lane >> 3) & 1) << 4);
    } else {
        bBase = sbase + ATILE_B +
                ((lane & 7) + (((lane >> 3) & 1) << 3)) * BROW +
                (wn * 32 + (lane >> 4) * 8) * 2;
    }
#pragma unroll
    for (int kh = 0; kh < 2; ++kh) {
        uint32_t af[4][4];
#pragma unroll
        for (int tm = 0; tm < 4; ++tm)
            ldmx4(af[tm], aBase + tm * 16 * SROW + kh * 32);
        uint32_t bfr[4][2];
#pragma unroll
        for (int tp = 0; tp < 2; ++tp) {
            uint32_t r[4];
            if (TRANSB) ldmx4(r, bBase + tp * 16 * SROW + kh * 32);
            else        ldmx4t(r, bBase + kh * 16 * BROW + tp * 32);
            bfr[2 * tp][0] = r[0];  bfr[2 * tp][1] = r[1];
            bfr[2 * tp + 1][0] = r[2]; bfr[2 * tp + 1][1] = r[3];
        }
#pragma unroll
        for (int tm = 0; tm < 4; ++tm)
#pragma unroll
            for (int tn = 0; tn < 4; ++tn)
                mma16816(acc[tm][tn], af[tm], bfr[tn]);
    }
}

template <int BN, bool TRANSB>
__global__ __launch_bounds__(2 * BN)
void tc_gemm(const bf16* __restrict__ A, const bf16* __restrict__ Bm,
             int M, int N, int K, int lda, int ldb, int ldc, int kparts,
             size_t aOff1, size_t bOff1, size_t cOff1B,
             size_t aOff2, size_t bOff2, size_t cOff2B,
             int mode, float scale,
             const float* __restrict__ bias, const float* __restrict__ gam,
             const float* __restrict__ bet, const float* __restrict__ mean,
             const float* __restrict__ var, const float* __restrict__ resid,
             const float* __restrict__ lsp,
             void* __restrict__ Cout)
{
    constexpr int NW = BN / 32;
    constexpr int BSTAGE = TRANSB ? BN * SROW : 32 * (2 * BN + 16);
    constexpr int STAGE = ATILE_B + BSTAGE;
    extern __shared__ char smem[];
    const uint32_t sb = s2u(smem);
    {
        const int z = blockIdx.z;
        const int part = z % kparts, bank = z / kparts;
        A    += bank * aOff2 + part * aOff1;
        Bm   += bank * bOff2 + part * bOff1;
        Cout  = (void*)((char*)Cout + (size_t)bank * cOff2B + (size_t)part * cOff1B);
    }
    const int tid  = threadIdx.x;
    const int lane = tid & 31;
    const int wid  = tid >> 5;
    const int wm = wid / NW, wn = wid % NW;
    const int m0 = blockIdx.y * 128;
    const int n0 = blockIdx.x * BN;
    const int NC = K >> 5;

    float acc[4][4][4];
#pragma unroll
    for (int a = 0; a < 4; ++a)
#pragma unroll
        for (int b = 0; b < 4; ++b)
#pragma unroll
            for (int c = 0; c < 4; ++c) acc[a][b][c] = 0.f;

#pragma unroll
    for (int s = 0; s < 2; ++s) {
        stage_load<BN, TRANSB>(A, Bm, N, K, lda, ldb, m0, n0, s * 32, sb + s * STAGE, tid);
        cp_commit();
    }

    for (int i = 0; i < NC; ++i) {
        asm volatile("cp.async.wait_group 1;" ::: "memory");
        __syncthreads();
        compute_stage<BN, TRANSB>(sb + (i % NSTAGE) * STAGE, lane, wm, wn, acc);
        if (i + 2 < NC)
            stage_load<BN, TRANSB>(A, Bm, N, K, lda, ldb, m0, n0, (i + 2) * 32,
                                   sb + ((i + 2) % NSTAGE) * STAGE, tid);
        cp_commit();
    }
    asm volatile("cp.async.wait_group 0;" ::: "memory");

    const float lsv = (mode == MODE_LS) ? __expf(lsp[0]) : 1.f;

#pragma unroll
    for (int tm = 0; tm < 4; ++tm) {
#pragma unroll
        for (int tn = 0; tn < 4; ++tn) {
            const int r0 = m0 + wm * 64 + tm * 16 + (lane >> 2);
            const int c0 = n0 + wn * 32 + tn * 8 + 2 * (lane & 3);
#pragma unroll
            for (int h = 0; h < 2; ++h) {
                const int row = r0 + 8 * h;
                const float f0 = acc[tm][tn][2 * h];
                const float f1 = acc[tm][tn][2 * h + 1];
                if (mode == MODE_SMUL) {
                    __nv_bfloat162 p = __floats2bfloat162_rn(f0 * scale, f1 * scale);
                    *reinterpret_cast<__nv_bfloat162*>(
                        (bf16*)Cout + (size_t)row * ldc + c0) = p;
                } else if (mode == MODE_BIAS) {
                    __nv_bfloat162 p = __floats2bfloat162_rn(f0 + bias[c0],
                                                             f1 + bias[c0 + 1]);
                    *reinterpret_cast<__nv_bfloat162*>(
                        (bf16*)Cout + (size_t)row * ldc + c0) = p;
                } else if (mode == MODE_PART) {
                    float* Cf = (float*)Cout + (size_t)row * ldc + c0;
                    Cf[0] = f0; Cf[1] = f1;
                } else if (mode == MODE_BNRELU) {
                    float x0 = f0 + bias[c0];
                    x0 = (x0 - mean[c0]) * rsqrtf(var[c0] + 1e-5f) * gam[c0] + bet[c0];
                    float x1 = f1 + bias[c0 + 1];
                    x1 = (x1 - mean[c0 + 1]) * rsqrtf(var[c0 + 1] + 1e-5f) * gam[c0 + 1]
                         + bet[c0 + 1];
                    __nv_bfloat162 p = __floats2bfloat162_rn(fmaxf(x0, 0.f),
                                                             fmaxf(x1, 0.f));
                    *reinterpret_cast<__nv_bfloat162*>(
                        (bf16*)Cout + (size_t)row * ldc + c0) = p;
                } else if (mode == MODE_RESID) {
                    float* Cf = (float*)Cout + (size_t)row * ldc + c0;
                    const float2 rv = *reinterpret_cast<const float2*>(
                        resid + (size_t)(row & (Bq - 1)) * ldc + c0);
                    float2 o;
                    o.x = f0 + bias[c0] + rv.x;
                    o.y = f1 + bias[c0 + 1] + rv.y;
                    *reinterpret_cast<float2*>(Cf) = o;
                } else { // MODE_LS
                    if (c0 < N) {
                        float* Cf = (float*)Cout + (size_t)row * ldc + c0;
                        Cf[0] = f0 * lsv;
                        Cf[1] = f1 * lsv;
                    }
                }
            }
        }
    }
}

#define SMEM_NT128 (NSTAGE * (ATILE_B + 128 * SROW))
#define SMEM_NT256 (NSTAGE * (ATILE_B + 256 * SROW))
#define SMEM_NN256 (NSTAGE * (ATILE_B + 32 * (2 * 256 + 16)))
#define SMEM_NN128 (NSTAGE * (ATILE_B + 32 * (2 * 128 + 16)))

// ---------------- flash attention: U = softmax(0.1 T H2^T) @ H2 -------------
// grid (32 qblocks, 2 banks, 2 kv-splits), 256 threads (8 warps x 16 q-rows).
// Per CTA: 128 q x 4096 keys, K-tiles of 128. d = 128.
#define FL_RS   272                       // smem row stride (256B data + 16 pad)
#define FL_TILE (128 * FL_RS)             // 34816
#define FL_SMEM (3 * FL_TILE)             // Q + 2 K stages = 104448

__global__ __launch_bounds__(256)
void flash_kernel(const bf16* __restrict__ Tq, const bf16* __restrict__ H2k,
                  float* __restrict__ Up, float* __restrict__ Um,
                  float* __restrict__ Ul)
{
    extern __shared__ char smem[];
    const uint32_t sQ = s2u(smem);
    const uint32_t sK = sQ + FL_TILE;
    const int tid = threadIdx.x, lane = tid & 31, wid = tid >> 5;
    const int qb = blockIdx.x, bank = blockIdx.y, split = blockIdx.z;
    const bf16* Q  = Tq + (size_t)qb * 128 * Pq;
    const bf16* KB = H2k + ((size_t)bank * Nq + (size_t)split * 4096) * Pq;

    // load Q tile (one group)
    for (int i = tid; i < 2048; i += 256) {
        const int r = i >> 4, ch = i & 15;
        cp16(sQ + r * FL_RS + ch * 16, Q + (size_t)r * Pq + ch * 8);
    }
    cp_commit();
    // prefetch K tile 0
    for (int i = tid; i < 2048; i += 256) {
        const int r = i >> 4, ch = i & 15;
        cp16(sK + r * FL_RS + ch * 16, KB + (size_t)r * Pq + ch * 8);
    }
    cp_commit();

    float m[2] = {-3e38f, -3e38f}, l[2] = {0.f, 0.f};
    float Uacc[16][4];
#pragma unroll
    for (int n = 0; n < 16; ++n)
#pragma unroll
        for (int e = 0; e < 4; ++e) Uacc[n][e] = 0.f;

    const uint32_t aQ = sQ + (wid * 16 + (lane & 15)) * FL_RS + (lane >> 4) * 16;
    const uint32_t bS0 = (((lane >> 4) << 3) + (lane & 7)) * FL_RS +
                         (((lane >> 3) & 1) << 4);
    const uint32_t bU0 = ((lane & 7) + (((lane >> 3) & 1) << 3)) * FL_RS +
                         ((lane >> 4) << 4);

    for (int t = 0; t < 32; ++t) {
        asm volatile("cp.async.wait_group 0;" ::: "memory");
        __syncthreads();
        const uint32_t cur = sK + (t & 1) * FL_TILE;
        if (t + 1 < 32) {
            const uint32_t nxt = sK + ((t + 1) & 1) * FL_TILE;
            const bf16* src = KB + (size_t)(t + 1) * 128 * Pq;
            for (int i = tid; i < 2048; i += 256) {
                const int r = i >> 4, ch = i & 15;
                cp16(nxt + r * FL_RS + ch * 16, src + (size_t)r * Pq + ch * 8);
            }
        }
        cp_commit();

        // ---- S = Q @ K^T (16 q-rows x 128 keys per warp) ----
        float S[16][4];
#pragma unroll
        for (int n = 0; n < 16; ++n)
#pragma unroll
            for (int e = 0; e < 4; ++e) S[n][e] = 0.f;
#pragma unroll
        for (int kh = 0; kh < 8; ++kh) {
            uint32_t af[4];
            ldmx4(af, aQ + kh * 16);
#pragma unroll
            for (int tp = 0; tp < 8; ++tp) {
                uint32_t r[4];
                ldmx4(r, cur + bS0 + tp * 16 * FL_RS + kh * 16);
                uint32_t b0[2] = {r[0], r[1]}, b1[2] = {r[2], r[3]};
                mma16816(S[2 * tp], af, b0);
                mma16816(S[2 * tp + 1], af, b1);
            }
        }

        // ---- online softmax (rows lane>>2 and +8) ----
#pragma unroll
        for (int h = 0; h < 2; ++h) {
            float tmax = -3e38f;
#pragma unroll
            for (int n = 0; n < 16; ++n)
                tmax = fmaxf(tmax, fmaxf(S[n][2 * h], S[n][2 * h + 1]));
            tmax = fmaxf(tmax, __shfl_xor_sync(0xffffffffu, tmax, 1));
            tmax = fmaxf(tmax, __shfl_xor_sync(0xffffffffu, tmax, 2));
            const float mn = fmaxf(m[h], 0.1f * tmax);
            const float alpha = __expf(m[h] - mn);
            float rs = 0.f;
#pragma unroll
            for (int n = 0; n < 16; ++n) {
#pragma unroll
                for (int e = 0; e < 2; ++e) {
                    const float p = __expf(0.1f * S[n][2 * h + e] - mn);
                    S[n][2 * h + e] = p;
                    rs += p;
                }
            }
            rs += __shfl_xor_sync(0xffffffffu, rs, 1);
            rs += __shfl_xor_sync(0xffffffffu, rs, 2);
            l[h] = l[h] * alpha + rs;
#pragma unroll
            for (int n = 0; n < 16; ++n) {
                Uacc[n][2 * h] *= alpha;
                Uacc[n][2 * h + 1] *= alpha;
            }
            m[h] = mn;
        }

        // ---- U += P @ K (P from S regs, layout-compatible A frags) ----
#pragma unroll
        for (int ku = 0; ku < 8; ++ku) {
            uint32_t a[4];
            a[0] = packbf2(S[2 * ku][0], S[2 * ku][1]);
            a[1] = packbf2(S[2 * ku][2], S[2 * ku][3]);
            a[2] = packbf2(S[2 * ku + 1][0], S[2 * ku + 1][1]);
            a[3] = packbf2(S[2 * ku + 1][2], S[2 * ku + 1][3]);
#pragma unroll
            for (int tp = 0; tp < 8; ++tp) {
                uint32_t r[4];
                ldmx4t(r, cur + bU0 + ku * 16 * FL_RS + tp * 32);
                uint32_t b0[2] = {r[0], r[1]}, b1[2] = {r[2], r[3]};
                mma16816(Uacc[2 * tp], a, b0);
                mma16816(Uacc[2 * tp + 1], a, b1);
            }
        }
    }

    // ---- write partials ----
    const size_t sbi = ((size_t)split * 2 + bank) * Bq;
    const int rowb = qb * 128 + wid * 16 + (lane >> 2);
#pragma unroll
    for (int h = 0; h < 2; ++h) {
        const int row = rowb + 8 * h;
        if ((lane & 3) == 0) { Um[sbi + row] = m[h]; Ul[sbi + row] = l[h]; }
#pragma unroll
        for (int n = 0; n < 16; ++n) {
            float2 v = make_float2(Uacc[n][2 * h], Uacc[n][2 * h + 1]);
            *reinterpret_cast<float2*>(
                Up + (sbi + row) * Pq + n * 8 + 2 * (lane & 3)) = v;
        }
    }
}

// merge the two kv-splits: Ucat = (a0 U0 + a1 U1) / (a0 l0 + a1 l1)
__global__ void combine_kernel(const float* __restrict__ Up,
                               const float* __restrict__ Um,
                               const float* __restrict__ Ul,
                               bf16* __restrict__ Ucat)
{
    const int row = blockIdx.x, bank = blockIdx.y, d = threadIdx.x;
    const size_t i0 = (size_t)bank * Bq + row;
    const size_t i1 = (size_t)(2 + bank) * Bq + row;
    const float m0 = Um[i0], m1 = Um[i1];
    const float mt = fmaxf(m0, m1);
    const float a0 = __expf(m0 - mt), a1 = __expf(m1 - mt);
    const float den = a0 * Ul[i0] + a1 * Ul[i1];
    const float v = (a0 * Up[i0 * Pq + d] + a1 * Up[i1 * Pq + d]) / den;
    Ucat[((size_t)bank * Bq + row) * Pq + d] = __float2bfloat16(v);
}

// ---------------- small kernels --------------------------------------------
__global__ void cvt_all_kernel(const float* __restrict__ Fv,
                               const float* __restrict__ Fvs,
                               const float* __restrict__ Fvt,
                               const float* __restrict__ W1,
                               const float* __restrict__ W2,
                               const float* __restrict__ Wp,
                               const float* __restrict__ W3,
                               bf16* __restrict__ xb, bf16* __restrict__ W1b,
                               bf16* __restrict__ W2b, bf16* __restrict__ Wpb,
                               bf16* __restrict__ W3T)
{
    const int nXB = Mall * Dq;
    const int nW1 = Pq * Dq;
    const int nW2 = Pq * Pq;
    const int nWp = Dq * Dq;
    const int nT1 = Pq * Dq;
    int i = (blockIdx.x * blockDim.x + threadIdx.x) * 4;
    const float* src = nullptr;
    bf16* dst;
    float f4[4];
    bool gather = false;
    if (i < nXB) {
        if (i < Bq * Dq)                  { src = Fv + i;  }
        else if (i < (Bq + Nq) * Dq)      { src = Fvs + (i - Bq * Dq); }
        else                              { src = Fvt + (i - (Bq + Nq) * Dq); }
        dst = xb + i;
    } else if ((i -= nXB) < nW1)          { src = W1 + i; dst = W1b + i; }
    else if ((i -= nW1) < nW2)            { src = W2 + i; dst = W2b + i; }
    else if ((i -= nW2) < nWp)            { src = Wp + i; dst = Wpb + i; }
    else if ((i -= nWp) < 3 * nT1) {
        const int g = i / nT1;
        const int r = i - g * nT1;
        const int j = r >> 10, d0 = r & 1023;
#pragma unroll
        for (int e = 0; e < 4; ++e)
            f4[e] = W3[(3 * (d0 + e) + g) * 128 + j];
        dst = W3T + i;
        gather = true;
    } else return;
    if (!gather) {
        const float4 v = *reinterpret_cast<const float4*>(src);
        f4[0] = v.x; f4[1] = v.y; f4[2] = v.z; f4[3] = v.w;
    }
    __nv_bfloat162 a = __floats2bfloat162_rn(f4[0], f4[1]);
    __nv_bfloat162 b = __floats2bfloat162_rn(f4[2], f4[3]);
    uint2 pk;
    pk.x = *reinterpret_cast<uint32_t*>(&a);
    pk.y = *reinterpret_cast<uint32_t*>(&b);
    *reinterpret_cast<uint2*>(dst) = pk;
}

// block 4: vb[j]; blocks 0-3: bv2
__global__ void prep_misc_kernel(const float* __restrict__ W3,
                                 const float* __restrict__ b3,
                                 const float* __restrict__ Wp,
                                 const float* __restrict__ bp,
                                 float* __restrict__ vb,
                                 float* __restrict__ bv2)
{
    if (blockIdx.x == 4) {
        if (threadIdx.x >= 128) return;
        const int j = threadIdx.x;
        float acc = 0.f;
        for (int d = 0; d < 1024; ++d)
            acc += b3[3 * d] * W3[(3 * d + 1) * 128 + j];
        vb[j] = acc;
    } else {
        const int i = blockIdx.x * 256 + threadIdx.x;
        float acc = 0.f;
        const float* wpr = Wp + (size_t)i * 1024;
        for (int d = 0; d < 1024; ++d)
            acc += wpr[d] * b3[3 * d + 2];
        bv2[i] = acc + bp[i];
    }
}

// sum split-K partials -> bf16
__global__ void reduce_parts(const float* __restrict__ in, bf16* __restrict__ out,
                             int n, int parts, int stride)
{
    const int i = blockIdx.x * blockDim.x + threadIdx.x;
    if (i >= n) return;
    float s = 0.f;
    for (int p = 0; p < parts; ++p) s += in[(size_t)p * stride + i];
    out[i] = __float2bfloat16(s);
}

// G row = norm(F0)+norm(F1); write Ap = [Gh|Gh|Gl] directly
__global__ void norm2_build_Ap(const float* __restrict__ F, bf16* __restrict__ Ap)
{
    const float* p0 = F + (size_t)blockIdx.x * 1024;
    const float* p1 = p0 + (size_t)Bq * 1024;
    const int tid = threadIdx.x;
    const int lane = tid & 31, w = tid >> 5;

    const float4 v0 = *reinterpret_cast<const float4*>(p0 + tid * 4);
    const float4 v1 = *reinterpret_cast<const float4*>(p1 + tid * 4);
    float s0 = v0.x * v0.x + v0.y * v0.y + v0.z * v0.z + v0.w * v0.w;
    float s1 = v1.x * v1.x + v1.y * v1.y + v1.z * v1.z + v1.w * v1.w;
#pragma unroll
    for (int o = 16; o > 0; o >>= 1) {
        s0 += __shfl_xor_sync(0xffffffffu, s0, o);
        s1 += __shfl_xor_sync(0xffffffffu, s1, o);
    }
    __shared__ float sh0[8], sh1[8];
    if (lane == 0) { sh0[w] = s0; sh1[w] = s1; }
    __syncthreads();
    if (tid == 0) {
        float t0 = 0.f, t1 = 0.f;
#pragma unroll
        for (int i = 0; i < 8; ++i) { t0 += sh0[i]; t1 += sh1[i]; }
        sh0[0] = t0; sh1[0] = t1;
    }
    __syncthreads();
    const float rn0 = rsqrtf(sh0[0]);
    const float rn1 = rsqrtf(sh1[0]);

    float g[4];
    g[0] = v0.x * rn0 + v1.x * rn1;
    g[1] = v0.y * rn0 + v1.y * rn1;
    g[2] = v0.z * rn0 + v1.z * rn1;
    g[3] = v0.w * rn0 + v1.w * rn1;

    bf16* row = Ap + (size_t)blockIdx.x * 3072;
    const int c = tid * 4;
    uint32_t hi[2], lo[2];
#pragma unroll
    for (int q = 0; q < 2; ++q) {
        const float x = g[2 * q], y = g[2 * q + 1];
        const bf16 hx = __float2bfloat16(x), hy = __float2bfloat16(y);
        hi[q] = packbf2(x, y);   // rn pack of the pair (same as individual rn)
        __nv_bfloat162 hl = __floats2bfloat162_rn(x - __bfloat162float(hx),
                                                  y - __bfloat162float(hy));
        lo[q] = *reinterpret_cast<uint32_t*>(&hl);
    }
    *reinterpret_cast<uint2*>(row + c)        = make_uint2(hi[0], hi[1]);
    *reinterpret_cast<uint2*>(row + 1024 + c) = make_uint2(hi[0], hi[1]);
    *reinterpret_cast<uint2*>(row + 2048 + c) = make_uint2(lo[0], lo[1]);
}

// B' = [Fh | Fl | Fh]
__global__ void build_Bp_kernel(const float* __restrict__ Ft, bf16* __restrict__ Bp)
{
    const int idx = blockIdx.x * blockDim.x + threadIdx.x;
    if (idx >= Cq * Dq) return;
    const int r = idx >> 10, c = idx & 1023;
    const float v = Ft[idx];
    const bf16 h = __float2bfloat16(v);
    const bf16 l = __float2bfloat16(v - __bfloat162float(h));
    bf16* row = Bp + (size_t)r * 3072;
    row[c] = h; row[1024 + c] = l; row[2048 + c] = h;
}

// ---------------- host side ------------------------------------------------
struct GemmArgs {
    const float *bias = nullptr, *gam = nullptr, *bet = nullptr;
    const float *mean = nullptr, *var = nullptr, *resid = nullptr, *lsp = nullptr;
    int lda = 0, ldb = 0, ldc = 0;
    int kparts = 1, gz = 1;
    size_t aOff1 = 0, bOff1 = 0, cOff1B = 0;
    size_t aOff2 = 0, bOff2 = 0, cOff2B = 0;
};

static void tc(bool transB, const bf16* A, const bf16* B, int M, int N, int K,
               int mode, float scale, void* C, const GemmArgs& g)
{
    const int lda = g.lda ? g.lda : K;
    const int ldb = g.ldb ? g.ldb : K;
    const int ldc = g.ldc ? g.ldc : N;
    if (!transB) {
        dim3 grid(N / 256, M / 128, g.gz);
        tc_gemm<256, false><<<grid, 512, SMEM_NN256>>>(A, B, M, N, K, lda, ldb, ldc,
            g.kparts, g.aOff1, g.bOff1, g.cOff1B, g.aOff2, g.bOff2, g.cOff2B,
            mode, scale, g.bias, g.gam, g.bet, g.mean, g.var, g.resid, g.lsp, C);
    } else if (N >= 256) {
        dim3 grid((N + 255) / 256, M / 128, g.gz);
        tc_gemm<256, true><<<grid, 512, SMEM_NT256>>>(A, B, M, N, K, lda, ldb, ldc,
            g.kparts, g.aOff1, g.bOff1, g.cOff1B, g.aOff2, g.bOff2, g.cOff2B,
            mode, scale, g.bias, g.gam, g.bet, g.mean, g.var, g.resid, g.lsp, C);
    } else {
        dim3 grid((N + 127) / 128, M / 128, g.gz);
        tc_gemm<128, true><<<grid, 256, SMEM_NT128>>>(A, B, M, N, K, lda, ldb, ldc,
            g.kparts, g.aOff1, g.bOff1, g.cOff1B, g.aOff2, g.bOff2, g.cOff2B,
            mode, scale, g.bias, g.gam, g.bet, g.mean, g.var, g.resid, g.lsp, C);
    }
}

extern "C" void kernel_launch(void* const* d_in, const int* in_sizes, int n_in,
                              void* d_out, int out_size)
{
    (void)in_sizes; (void)n_in; (void)out_size;
    const float* Ft  = (const float*)d_in[0];
    const float* Fv  = (const float*)d_in[1];
    const float* Fvs = (const float*)d_in[2];
    const float* Fvt = (const float*)d_in[3];
    const float* W1  = (const float*)d_in[4];
    const float* b1  = (const float*)d_in[5];
    const float* g1  = (const float*)d_in[6];
    const float* be1 = (const float*)d_in[7];
    const float* m1  = (const float*)d_in[8];
    const float* v1  = (const float*)d_in[9];
    const float* W2  = (const float*)d_in[10];
    const float* b2  = (const float*)d_in[11];
    const float* g2  = (const float*)d_in[12];
    const float* be2 = (const float*)d_in[13];
    const float* m2  = (const float*)d_in[14];
    const float* v2  = (const float*)d_in[15];
    const float* W3  = (const float*)d_in[16];
    const float* b3  = (const float*)d_in[17];
    const float* Wp  = (const float*)d_in[18];
    const float* bp  = (const float*)d_in[19];
    const float* ls  = (const float*)d_in[20];
    float* out = (float*)d_out;

    cudaFuncSetAttribute((const void*)tc_gemm<128, true>,
                         cudaFuncAttributeMaxDynamicSharedMemorySize, SMEM_NT128);
    cudaFuncSetAttribute((const void*)tc_gemm<256, true>,
                         cudaFuncAttributeMaxDynamicSharedMemorySize, SMEM_NT256);
    cudaFuncSetAttribute((const void*)tc_gemm<256, false>,
                         cudaFuncAttributeMaxDynamicSharedMemorySize, SMEM_NN256);
    cudaFuncSetAttribute((const void*)flash_kernel,
                         cudaFuncAttributeMaxDynamicSharedMemorySize, FL_SMEM);

    bf16 *xb, *W1b, *W2b, *Wpb, *W3T, *H1b, *H2b, *Mt, *Wvp, *T, *Ucat, *Ap, *Bp;
    float *vb, *bv2, *F, *Up, *Um, *Ul, *MtP, *WvpP;
    cudaGetSymbolAddress((void**)&xb,   g_xb);
    cudaGetSymbolAddress((void**)&W1b,  g_W1b);
    cudaGetSymbolAddress((void**)&W2b,  g_W2b);
    cudaGetSymbolAddress((void**)&Wpb,  g_Wpb);
    cudaGetSymbolAddress((void**)&W3T,  g_W3T);
    cudaGetSymbolAddress((void**)&H1b,  g_H1b);
    cudaGetSymbolAddress((void**)&H2b,  g_H2b);
    cudaGetSymbolAddress((void**)&Mt,   g_Mt);
    cudaGetSymbolAddress((void**)&vb,   g_vb);
    cudaGetSymbolAddress((void**)&Wvp,  g_Wvp);
    cudaGetSymbolAddress((void**)&bv2,  g_bv2);
    cudaGetSymbolAddress((void**)&T,    g_T);
    cudaGetSymbolAddress((void**)&Ucat, g_Ucat);
    cudaGetSymbolAddress((void**)&Up,   g_Up);
    cudaGetSymbolAddress((void**)&Um,   g_Um);
    cudaGetSymbolAddress((void**)&Ul,   g_Ul);
    cudaGetSymbolAddress((void**)&MtP,  g_MtP);
    cudaGetSymbolAddress((void**)&WvpP, g_WvpP);
    cudaGetSymbolAddress((void**)&F,    g_F);
    cudaGetSymbolAddress((void**)&Ap,   g_Ap);
    cudaGetSymbolAddress((void**)&Bp,   g_Bp);

    // conversions + bias precomputes
    {
        const int total = Mall * Dq + Pq * Dq + Pq * Pq + Dq * Dq + 3 * Pq * Dq;
        cvt_all_kernel<<<(total / 4 + 255) / 256, 256>>>(
            Fv, Fvs, Fvt, W1, W2, Wp, W3, xb, W1b, W2b, Wpb, W3T);
    }
    prep_misc_kernel<<<5, 256>>>(W3, b3, Wp, bp, vb, bv2);

    // Mt = (W3q^T W3k)^T, split-K x8
    {
        GemmArgs a; a.lda = 1024; a.ldb = 1024; a.ldc = 128;
        a.kparts = 8; a.gz = 8;
        a.aOff1 = 128; a.bOff1 = 128; a.cOff1B = (size_t)128 * 128 * 4;
        tc(true, W3T + Pq * Dq, W3T, Pq, Pq, 128, MODE_PART, 1.f, MtP, a);
    }
    // Wvp = Wp @ W3v, split-K x4
    {
        GemmArgs a; a.lda = 1024; a.ldb = 1024; a.ldc = 128;
        a.kparts = 4; a.gz = 4;
        a.aOff1 = 256; a.bOff1 = 256; a.cOff1B = (size_t)1024 * 128 * 4;
        tc(true, Wpb, W3T + 2 * Pq * Dq, Dq, Pq, 256, MODE_PART, 1.f, WvpP, a);
    }
    reduce_parts<<<(16384 + 255) / 256, 256>>>(MtP, Mt, 16384, 8, 16384);
    reduce_parts<<<(131072 + 255) / 256, 256>>>(WvpP, Wvp, 131072, 4, 131072);

    // pre_project -> H2
    {
        GemmArgs a; a.bias = b1; a.gam = g1; a.bet = be1; a.mean = m1; a.var = v1;
        tc(true, xb, W1b, Mall, Pq, Dq, MODE_BNRELU, 1.f, H1b, a);
    }
    {
        GemmArgs a; a.bias = b2; a.gam = g2; a.bet = be2; a.mean = m2; a.var = v2;
        tc(true, H1b, W2b, Mall, Pq, Pq, MODE_BNRELU, 1.f, H2b, a);
    }

    // T = H2q @ Mt^T + v
    {
        GemmArgs a; a.bias = vb;
        tc(true, H2b, Mt, Bq, Pq, Pq, MODE_BIAS, 1.f, T, a);
    }

    // flash attention: U partials over (qb, bank, split)
    flash_kernel<<<dim3(Bq / 128, 2, 2), 256, FL_SMEM>>>(
        T, H2b + (size_t)Bq * Pq, Up, Um, Ul);
    combine_kernel<<<dim3(Bq, 2), 128>>>(Up, Um, Ul, Ucat);

    // F = Fv + Ucat @ Wvp^T + bv2 (per bank)
    {
        GemmArgs a; a.bias = bv2; a.resid = Fv;
        a.gz = 2;
        a.aOff2 = (size_t)Bq * Pq;
        a.cOff2B = (size_t)Bq * Dq * sizeof(float);
        tc(true, Ucat, Wvp, Bq, Dq, Pq, MODE_RESID, 1.f, F, a);
    }

    // normalize + build Ap, Bp, final GEMM
    norm2_build_Ap<<<Bq, 256>>>(F, Ap);
    build_Bp_kernel<<<(Cq * Dq + 255) / 256, 256>>>(Ft, Bp);
    {
        GemmArgs a; a.lsp = ls;
        tc(true, Ap, Bp, Bq, Cq, 3 * Dq, MODE_LS, 1.f, out, a);
    }
}